// round 1
// baseline (speedup 1.0000x reference)
#include <cuda_runtime.h>
#include <math.h>

#define E_EXP   16
#define TOPK    2
#define D_IN    256
#define D_H     512
#define D_OUT   256
#define BATCH   32768

#define TM      64      // tokens per MLP tile
#define TNC     128     // N chunk
#define TK      32      // K chunk

// ---------------- scratch (__device__ globals; no allocs allowed) ----------
__device__ int   g_counts[E_EXP];
__device__ int   g_offsets[E_EXP + 1];
__device__ int   g_cursor[E_EXP];
__device__ int   g_topk_e[BATCH * TOPK];
__device__ float g_topk_w[BATCH * TOPK];
__device__ int   g_perm[BATCH * TOPK];
__device__ float g_y[(size_t)BATCH * TOPK * D_OUT];   // 64 MB per-slot expert outputs

// ---------------- reset ----------------------------------------------------
__global__ void reset_kernel() {
    int i = threadIdx.x;
    if (i < E_EXP) g_counts[i] = 0;
}

// ---------------- gating: 1 warp per token ---------------------------------
// logits = x @ Wg + bg ; top-2 ; w0 = 1/(1+exp(l1-l0)) (softmax denom cancels)
__global__ void gating_kernel(const float* __restrict__ x,
                              const float* __restrict__ Wg,
                              const float* __restrict__ bg) {
    int warp = (blockIdx.x * blockDim.x + threadIdx.x) >> 5;
    int lane = threadIdx.x & 31;
    if (warp >= BATCH) return;
    const float* xr = x + (size_t)warp * D_IN;

    float acc[E_EXP];
#pragma unroll
    for (int e = 0; e < E_EXP; e++) acc[e] = 0.f;

#pragma unroll
    for (int i = 0; i < D_IN / 32; i++) {
        float xv = xr[i * 32 + lane];
        const float* wr = Wg + (size_t)(i * 32 + lane) * E_EXP;
#pragma unroll
        for (int e = 0; e < E_EXP; e++) acc[e] = fmaf(xv, wr[e], acc[e]);
    }
#pragma unroll
    for (int e = 0; e < E_EXP; e++) {
        float v = acc[e];
        v += __shfl_xor_sync(0xffffffffu, v, 16);
        v += __shfl_xor_sync(0xffffffffu, v, 8);
        v += __shfl_xor_sync(0xffffffffu, v, 4);
        v += __shfl_xor_sync(0xffffffffu, v, 2);
        v += __shfl_xor_sync(0xffffffffu, v, 1);
        acc[e] = v + bg[e];
    }
    if (lane == 0) {
        int i0 = 0; float v0 = acc[0];
#pragma unroll
        for (int e = 1; e < E_EXP; e++)
            if (acc[e] > v0) { v0 = acc[e]; i0 = e; }
        int i1 = -1; float v1 = -3.4e38f;
#pragma unroll
        for (int e = 0; e < E_EXP; e++)
            if (e != i0 && acc[e] > v1) { v1 = acc[e]; i1 = e; }
        float w0 = 1.f / (1.f + expf(v1 - v0));
        g_topk_e[warp * 2 + 0] = i0;
        g_topk_e[warp * 2 + 1] = i1;
        g_topk_w[warp * 2 + 0] = w0;
        g_topk_w[warp * 2 + 1] = 1.f - w0;
        atomicAdd(&g_counts[i0], 1);
        atomicAdd(&g_counts[i1], 1);
    }
}

// ---------------- 16-bin exclusive scan ------------------------------------
__global__ void scan_kernel() {
    if (threadIdx.x == 0) {
        int s = 0;
        for (int e = 0; e < E_EXP; e++) {
            g_offsets[e] = s;
            g_cursor[e]  = s;
            s += g_counts[e];
        }
        g_offsets[E_EXP] = s;
    }
}

// ---------------- scatter entries into per-expert lists --------------------
// List order is nondeterministic, but each output row depends only on its own
// token's x, so values are order-invariant.
__global__ void scatter_kernel() {
    int i = blockIdx.x * blockDim.x + threadIdx.x;
    if (i >= BATCH * TOPK) return;
    int e = g_topk_e[i];
    int pos = atomicAdd(&g_cursor[e], 1);
    g_perm[pos] = i;
}

// ---------------- fused per-expert MLP (fp32 register-tiled) ---------------
// Block = (expert e, tile of TM entries). 256 threads as 16x16; each thread
// owns a 4x8 micro-tile (rows ty+16i, cols tx+16j).
// Stage 1: H[64,512] = relu(Xg @ W1[e] + b1[e])  -> smem
// Stage 2: y[slot]   = w * (H @ W2[e] + b2[e])   -> gmem per-slot buffer
__global__ void __launch_bounds__(256, 1)
expert_mlp_kernel(const float* __restrict__ x,
                  const float* __restrict__ W1,
                  const float* __restrict__ b1,
                  const float* __restrict__ W2,
                  const float* __restrict__ b2) {
    int e    = blockIdx.y;
    int tile = blockIdx.x;
    int beg = g_offsets[e];
    int cnt = g_offsets[e + 1] - beg;
    int m0  = tile * TM;
    if (m0 >= cnt) return;

    extern __shared__ float sm[];
    float* Hs = sm;                                   // [TM][D_H+1]
    float* Xs = Hs + TM * (D_H + 1);                  // [TM][TK+1]
    float* Ws = Xs + TM * (TK + 1);                   // [TK][TNC]
    int*   srow   = (int*)(Ws + TK * TNC);            // [TM]
    int*   sentry = srow + TM;                        // [TM]
    float* sw     = (float*)(sentry + TM);            // [TM]

    if (threadIdx.x < TM) {
        int g = beg + m0 + threadIdx.x;
        if (threadIdx.x + m0 < cnt) {
            int entry = g_perm[g];
            srow[threadIdx.x]   = entry >> 1;
            sentry[threadIdx.x] = entry;
            sw[threadIdx.x]     = g_topk_w[entry];
        } else {
            srow[threadIdx.x]   = 0;
            sentry[threadIdx.x] = -1;
            sw[threadIdx.x]     = 0.f;
        }
    }
    __syncthreads();

    int tx = threadIdx.x & 15;
    int ty = threadIdx.x >> 4;
    const float* W1e = W1 + (size_t)e * D_IN * D_H;
    const float* W2e = W2 + (size_t)e * D_H * D_OUT;
    float acc[4][8];

    // ---------------- stage 1 ----------------
    for (int nc = 0; nc < D_H / TNC; nc++) {
#pragma unroll
        for (int i = 0; i < 4; i++)
#pragma unroll
            for (int j = 0; j < 8; j++) acc[i][j] = 0.f;

        for (int kt = 0; kt < D_IN / TK; kt++) {
#pragma unroll
            for (int i = 0; i < (TM * TK) / 256; i++) {        // 8
                int idx = threadIdx.x + i * 256;
                int r = idx >> 5, c = idx & 31;
                Xs[r * (TK + 1) + c] = x[(size_t)srow[r] * D_IN + kt * TK + c];
            }
#pragma unroll
            for (int i = 0; i < (TK * TNC) / 256; i++) {       // 16
                int idx = threadIdx.x + i * 256;
                int kk = idx >> 7, n = idx & 127;
                Ws[kk * TNC + n] = W1e[(size_t)(kt * TK + kk) * D_H + nc * TNC + n];
            }
            __syncthreads();
#pragma unroll
            for (int kk = 0; kk < TK; kk++) {
                float a[4], bb[8];
#pragma unroll
                for (int i = 0; i < 4; i++) a[i] = Xs[(ty + 16 * i) * (TK + 1) + kk];
#pragma unroll
                for (int j = 0; j < 8; j++) bb[j] = Ws[kk * TNC + tx + 16 * j];
#pragma unroll
                for (int i = 0; i < 4; i++)
#pragma unroll
                    for (int j = 0; j < 8; j++)
                        acc[i][j] = fmaf(a[i], bb[j], acc[i][j]);
            }
            __syncthreads();
        }
        // epilogue: bias + relu -> Hs
#pragma unroll
        for (int i = 0; i < 4; i++) {
            int r = ty + 16 * i;
#pragma unroll
            for (int j = 0; j < 8; j++) {
                int gn = nc * TNC + tx + 16 * j;
                float v = acc[i][j] + b1[e * D_H + gn];
                Hs[r * (D_H + 1) + gn] = v > 0.f ? v : 0.f;
            }
        }
    }
    __syncthreads();

    // ---------------- stage 2 ----------------
    for (int nc = 0; nc < D_OUT / TNC; nc++) {
#pragma unroll
        for (int i = 0; i < 4; i++)
#pragma unroll
            for (int j = 0; j < 8; j++) acc[i][j] = 0.f;

        for (int kt = 0; kt < D_H / TK; kt++) {
#pragma unroll
            for (int i = 0; i < (TK * TNC) / 256; i++) {       // 16
                int idx = threadIdx.x + i * 256;
                int kk = idx >> 7, n = idx & 127;
                Ws[kk * TNC + n] = W2e[(size_t)(kt * TK + kk) * D_OUT + nc * TNC + n];
            }
            __syncthreads();
#pragma unroll
            for (int kk = 0; kk < TK; kk++) {
                float a[4], bb[8];
#pragma unroll
                for (int i = 0; i < 4; i++)
                    a[i] = Hs[(ty + 16 * i) * (D_H + 1) + kt * TK + kk];
#pragma unroll
                for (int j = 0; j < 8; j++) bb[j] = Ws[kk * TNC + tx + 16 * j];
#pragma unroll
                for (int i = 0; i < 4; i++)
#pragma unroll
                    for (int j = 0; j < 8; j++)
                        acc[i][j] = fmaf(a[i], bb[j], acc[i][j]);
            }
            __syncthreads();
        }
        // epilogue: bias, gate weight, scatter to per-slot buffer
#pragma unroll
        for (int i = 0; i < 4; i++) {
            int r = ty + 16 * i;
            int entry = sentry[r];
            if (entry >= 0) {
                float w = sw[r];
#pragma unroll
                for (int j = 0; j < 8; j++) {
                    int gn = nc * TNC + tx + 16 * j;
                    g_y[(size_t)entry * D_OUT + gn] = w * (acc[i][j] + b2[e * D_OUT + gn]);
                }
            }
        }
    }
}

// ---------------- combine the two expert slots per token -------------------
__global__ void combine_kernel(float* __restrict__ out) {
    int i = blockIdx.x * blockDim.x + threadIdx.x;     // over BATCH * (D_OUT/4)
    int b = i >> 6, q = i & 63;
    const float4* y4 = (const float4*)g_y;
    float4 u = y4[(size_t)(b * 2 + 0) * (D_OUT / 4) + q];
    float4 v = y4[(size_t)(b * 2 + 1) * (D_OUT / 4) + q];
    float4 o;
    o.x = u.x + v.x; o.y = u.y + v.y; o.z = u.z + v.z; o.w = u.w + v.w;
    ((float4*)out)[i] = o;
}

// ---------------- launch ----------------------------------------------------
extern "C" void kernel_launch(void* const* d_in, const int* in_sizes, int n_in,
                              void* d_out, int out_size) {
    const float* x  = (const float*)d_in[0];
    const float* Wg = (const float*)d_in[1];
    const float* bg = (const float*)d_in[2];
    const float* W1 = (const float*)d_in[3];
    const float* b1 = (const float*)d_in[4];
    const float* W2 = (const float*)d_in[5];
    const float* b2 = (const float*)d_in[6];
    float* out = (float*)d_out;

    const int SMEM_BYTES =
        (TM * (D_H + 1) + TM * (TK + 1) + TK * TNC) * 4 + TM * 12;

    static bool attr_set = false;
    if (!attr_set) {
        cudaFuncSetAttribute(expert_mlp_kernel,
                             cudaFuncAttributeMaxDynamicSharedMemorySize,
                             SMEM_BYTES);
        attr_set = true;
    }

    reset_kernel<<<1, 32>>>();
    gating_kernel<<<BATCH / 8, 256>>>(x, Wg, bg);
    scan_kernel<<<1, 32>>>();
    scatter_kernel<<<(BATCH * TOPK + 255) / 256, 256>>>();
    expert_mlp_kernel<<<dim3(BATCH / TM, E_EXP), 256, SMEM_BYTES>>>(x, W1, b1, W2, b2);
    combine_kernel<<<(BATCH * (D_OUT / 4)) / 256, 256>>>(out);
}

// round 2
// speedup vs baseline: 1.6061x; 1.6061x over previous
#include <cuda_runtime.h>
#include <math.h>

typedef unsigned long long u64;

#define E_EXP   16
#define TOPK    2
#define D_IN    256
#define D_H     512
#define D_OUT   256
#define BATCH   32768

#define TM      64      // tokens per MLP tile
#define TNC     128     // N chunk
#define TK      32      // K chunk

#define XS_STRIDE (D_IN + 4)   // 260 (float4-aligned rows, even for float2 loads)
#define HS_STRIDE (D_H + 2)    // 514 (even => aligned float2 loads)

// ---------------- scratch (__device__ globals; no allocs allowed) ----------
__device__ int   g_counts[E_EXP];
__device__ int   g_offsets[E_EXP + 1];
__device__ int   g_cursor[E_EXP];
__device__ int   g_topk_e[BATCH * TOPK];
__device__ float g_topk_w[BATCH * TOPK];
__device__ int   g_perm[BATCH * TOPK];
__device__ float g_y[(size_t)BATCH * TOPK * D_OUT];   // 64 MB per-slot expert outputs

// ---------------- packed fp32x2 helpers ------------------------------------
__device__ __forceinline__ void ffma2(u64 &d, u64 a, u64 b) {
    asm("fma.rn.f32x2 %0, %1, %2, %0;" : "+l"(d) : "l"(a), "l"(b));
}
__device__ __forceinline__ u64 bcast2(float v) {
    u64 r; asm("mov.b64 %0, {%1, %1};" : "=l"(r) : "f"(v)); return r;
}
__device__ __forceinline__ float2 unpack2(u64 v) {
    float2 r; asm("mov.b64 {%0, %1}, %2;" : "=f"(r.x), "=f"(r.y) : "l"(v)); return r;
}

// ---------------- reset ----------------------------------------------------
__global__ void reset_kernel() {
    int i = threadIdx.x;
    if (i < E_EXP) g_counts[i] = 0;
}

// ---------------- gating: 1 warp per token ---------------------------------
__global__ void gating_kernel(const float* __restrict__ x,
                              const float* __restrict__ Wg,
                              const float* __restrict__ bg) {
    int warp = (blockIdx.x * blockDim.x + threadIdx.x) >> 5;
    int lane = threadIdx.x & 31;
    if (warp >= BATCH) return;
    const float* xr = x + (size_t)warp * D_IN;

    float acc[E_EXP];
#pragma unroll
    for (int e = 0; e < E_EXP; e++) acc[e] = 0.f;

#pragma unroll
    for (int i = 0; i < D_IN / 32; i++) {
        float xv = xr[i * 32 + lane];
        const float* wr = Wg + (size_t)(i * 32 + lane) * E_EXP;
#pragma unroll
        for (int e = 0; e < E_EXP; e++) acc[e] = fmaf(xv, wr[e], acc[e]);
    }
#pragma unroll
    for (int e = 0; e < E_EXP; e++) {
        float v = acc[e];
        v += __shfl_xor_sync(0xffffffffu, v, 16);
        v += __shfl_xor_sync(0xffffffffu, v, 8);
        v += __shfl_xor_sync(0xffffffffu, v, 4);
        v += __shfl_xor_sync(0xffffffffu, v, 2);
        v += __shfl_xor_sync(0xffffffffu, v, 1);
        acc[e] = v + bg[e];
    }
    if (lane == 0) {
        int i0 = 0; float v0 = acc[0];
#pragma unroll
        for (int e = 1; e < E_EXP; e++)
            if (acc[e] > v0) { v0 = acc[e]; i0 = e; }
        int i1 = -1; float v1 = -3.4e38f;
#pragma unroll
        for (int e = 0; e < E_EXP; e++)
            if (e != i0 && acc[e] > v1) { v1 = acc[e]; i1 = e; }
        float w0 = 1.f / (1.f + expf(v1 - v0));
        g_topk_e[warp * 2 + 0] = i0;
        g_topk_e[warp * 2 + 1] = i1;
        g_topk_w[warp * 2 + 0] = w0;
        g_topk_w[warp * 2 + 1] = 1.f - w0;
        atomicAdd(&g_counts[i0], 1);
        atomicAdd(&g_counts[i1], 1);
    }
}

// ---------------- 16-bin exclusive scan ------------------------------------
__global__ void scan_kernel() {
    if (threadIdx.x == 0) {
        int s = 0;
        for (int e = 0; e < E_EXP; e++) {
            g_offsets[e] = s;
            g_cursor[e]  = s;
            s += g_counts[e];
        }
        g_offsets[E_EXP] = s;
    }
}

// ---------------- scatter: block-aggregated atomics ------------------------
__global__ void scatter_kernel() {
    __shared__ int hist[E_EXP];
    __shared__ int base[E_EXP];
    int tid = threadIdx.x;
    if (tid < E_EXP) hist[tid] = 0;
    __syncthreads();
    int i = blockIdx.x * 256 + tid;              // B*TOPK divisible by 256
    int e = g_topk_e[i];
    int rank = atomicAdd(&hist[e], 1);
    __syncthreads();
    if (tid < E_EXP) base[tid] = atomicAdd(&g_cursor[tid], hist[tid]);
    __syncthreads();
    g_perm[base[e] + rank] = i;
}

// ---------------- fused per-expert MLP (packed fp32x2 FFMA2) ---------------
// 256 threads as 16x16; thread (tx,ty) owns rows ty+16i (i<4) and column
// PAIRS (2tx+32j, 2tx+32j+1) (j<4)  => 4x4 packed accumulators = 4x8 scalar.
// Full X tile [64,256] resident in smem; W tiles register-prefetched.
__global__ void __launch_bounds__(256, 1)
expert_mlp_kernel(const float* __restrict__ x,
                  const float* __restrict__ W1,
                  const float* __restrict__ b1,
                  const float* __restrict__ W2,
                  const float* __restrict__ b2) {
    int e    = blockIdx.y;
    int tile = blockIdx.x;
    int beg = g_offsets[e];
    int cnt = g_offsets[e + 1] - beg;
    int m0  = tile * TM;
    if (m0 >= cnt) return;

    extern __shared__ float sm[];
    float* Hs = sm;                                   // [TM][HS_STRIDE]
    float* Xs = Hs + TM * HS_STRIDE;                  // [TM][XS_STRIDE]
    float* Ws = Xs + TM * XS_STRIDE;                  // [TK][TNC]
    int*   srow   = (int*)(Ws + TK * TNC);            // [TM]
    int*   sentry = srow + TM;                        // [TM]
    float* sw     = (float*)(sentry + TM);            // [TM]

    int tid = threadIdx.x;
    if (tid < TM) {
        int g = beg + m0 + tid;
        if (tid + m0 < cnt) {
            int entry = g_perm[g];
            srow[tid]   = entry >> 1;
            sentry[tid] = entry;
            sw[tid]     = g_topk_w[entry];
        } else {
            srow[tid]   = 0;
            sentry[tid] = -1;
            sw[tid]     = 0.f;
        }
    }
    __syncthreads();

    // ---- load full X tile [64 rows x 256 cols] into smem (float4) ----
#pragma unroll
    for (int i = 0; i < 16; i++) {                    // 4096 float4 / 256 thr
        int idx = tid + i * 256;
        int r = idx >> 6, q = idx & 63;               // q: float4 index in row
        float4 v = *(const float4*)&x[(size_t)srow[r] * D_IN + 4 * q];
        *(float4*)&Xs[r * XS_STRIDE + 4 * q] = v;
    }

    int tx = threadIdx.x & 15;
    int ty = threadIdx.x >> 4;
    const float* W1e = W1 + (size_t)e * D_IN * D_H;
    const float* W2e = W2 + (size_t)e * D_H * D_OUT;

    u64 acc[4][4];
    float4 pw[4];

    // ================= stage 1: H = relu(X @ W1 + b1) =================
    for (int nc = 0; nc < D_H / TNC; nc++) {
#pragma unroll
        for (int i = 0; i < 4; i++)
#pragma unroll
            for (int j = 0; j < 4; j++) acc[i][j] = 0ull;

        // prefetch kt=0
#pragma unroll
        for (int i = 0; i < 4; i++) {
            int idx = tid + i * 256;
            int kk = idx >> 5, q = idx & 31;
            pw[i] = *(const float4*)&W1e[(size_t)kk * D_H + nc * TNC + 4 * q];
        }

        for (int kt = 0; kt < D_IN / TK; kt++) {
#pragma unroll
            for (int i = 0; i < 4; i++) {
                int idx = tid + i * 256;
                int kk = idx >> 5, q = idx & 31;
                *(float4*)&Ws[kk * TNC + 4 * q] = pw[i];
            }
            __syncthreads();
            if (kt + 1 < D_IN / TK) {
#pragma unroll
                for (int i = 0; i < 4; i++) {
                    int idx = tid + i * 256;
                    int kk = idx >> 5, q = idx & 31;
                    pw[i] = *(const float4*)&W1e[(size_t)((kt + 1) * TK + kk) * D_H + nc * TNC + 4 * q];
                }
            }
#pragma unroll
            for (int kk = 0; kk < TK; kk += 2) {
                float2 a01[4];
#pragma unroll
                for (int i = 0; i < 4; i++)
                    a01[i] = *(const float2*)&Xs[(ty + 16 * i) * XS_STRIDE + kt * TK + kk];
                u64 b0[4], b1r[4];
#pragma unroll
                for (int j = 0; j < 4; j++) {
                    b0[j]  = *(const u64*)&Ws[kk * TNC + 2 * tx + 32 * j];
                    b1r[j] = *(const u64*)&Ws[(kk + 1) * TNC + 2 * tx + 32 * j];
                }
#pragma unroll
                for (int i = 0; i < 4; i++) {
                    u64 alo = bcast2(a01[i].x);
                    u64 ahi = bcast2(a01[i].y);
#pragma unroll
                    for (int j = 0; j < 4; j++) {
                        ffma2(acc[i][j], alo, b0[j]);
                        ffma2(acc[i][j], ahi, b1r[j]);
                    }
                }
            }
            __syncthreads();
        }
        // epilogue: bias + relu -> Hs (float2 stores)
#pragma unroll
        for (int i = 0; i < 4; i++) {
            int r = ty + 16 * i;
#pragma unroll
            for (int j = 0; j < 4; j++) {
                int gn = nc * TNC + 2 * tx + 32 * j;
                float2 v = unpack2(acc[i][j]);
                v.x += b1[e * D_H + gn];
                v.y += b1[e * D_H + gn + 1];
                v.x = v.x > 0.f ? v.x : 0.f;
                v.y = v.y > 0.f ? v.y : 0.f;
                *(float2*)&Hs[r * HS_STRIDE + gn] = v;
            }
        }
    }

    // ================= stage 2: y = w * (H @ W2 + b2) =================
    for (int nc = 0; nc < D_OUT / TNC; nc++) {
#pragma unroll
        for (int i = 0; i < 4; i++)
#pragma unroll
            for (int j = 0; j < 4; j++) acc[i][j] = 0ull;

#pragma unroll
        for (int i = 0; i < 4; i++) {
            int idx = tid + i * 256;
            int kk = idx >> 5, q = idx & 31;
            pw[i] = *(const float4*)&W2e[(size_t)kk * D_OUT + nc * TNC + 4 * q];
        }

        for (int kt = 0; kt < D_H / TK; kt++) {
#pragma unroll
            for (int i = 0; i < 4; i++) {
                int idx = tid + i * 256;
                int kk = idx >> 5, q = idx & 31;
                *(float4*)&Ws[kk * TNC + 4 * q] = pw[i];
            }
            __syncthreads();            // also orders stage-1 Hs writes before reads
            if (kt + 1 < D_H / TK) {
#pragma unroll
                for (int i = 0; i < 4; i++) {
                    int idx = tid + i * 256;
                    int kk = idx >> 5, q = idx & 31;
                    pw[i] = *(const float4*)&W2e[(size_t)((kt + 1) * TK + kk) * D_OUT + nc * TNC + 4 * q];
                }
            }
#pragma unroll
            for (int kk = 0; kk < TK; kk += 2) {
                float2 a01[4];
#pragma unroll
                for (int i = 0; i < 4; i++)
                    a01[i] = *(const float2*)&Hs[(ty + 16 * i) * HS_STRIDE + kt * TK + kk];
                u64 b0[4], b1r[4];
#pragma unroll
                for (int j = 0; j < 4; j++) {
                    b0[j]  = *(const u64*)&Ws[kk * TNC + 2 * tx + 32 * j];
                    b1r[j] = *(const u64*)&Ws[(kk + 1) * TNC + 2 * tx + 32 * j];
                }
#pragma unroll
                for (int i = 0; i < 4; i++) {
                    u64 alo = bcast2(a01[i].x);
                    u64 ahi = bcast2(a01[i].y);
#pragma unroll
                    for (int j = 0; j < 4; j++) {
                        ffma2(acc[i][j], alo, b0[j]);
                        ffma2(acc[i][j], ahi, b1r[j]);
                    }
                }
            }
            __syncthreads();
        }
        // epilogue: bias, gate weight, per-slot scatter (float2 stores)
#pragma unroll
        for (int i = 0; i < 4; i++) {
            int r = ty + 16 * i;
            int entry = sentry[r];
            if (entry >= 0) {
                float w = sw[r];
#pragma unroll
                for (int j = 0; j < 4; j++) {
                    int gn = nc * TNC + 2 * tx + 32 * j;
                    float2 v = unpack2(acc[i][j]);
                    v.x = w * (v.x + b2[e * D_OUT + gn]);
                    v.y = w * (v.y + b2[e * D_OUT + gn + 1]);
                    *(float2*)&g_y[(size_t)entry * D_OUT + gn] = v;
                }
            }
        }
    }
}

// ---------------- combine the two expert slots per token -------------------
__global__ void combine_kernel(float* __restrict__ out) {
    int i = blockIdx.x * blockDim.x + threadIdx.x;     // over BATCH * (D_OUT/4)
    int b = i >> 6, q = i & 63;
    const float4* y4 = (const float4*)g_y;
    float4 u = y4[(size_t)(b * 2 + 0) * (D_OUT / 4) + q];
    float4 v = y4[(size_t)(b * 2 + 1) * (D_OUT / 4) + q];
    float4 o;
    o.x = u.x + v.x; o.y = u.y + v.y; o.z = u.z + v.z; o.w = u.w + v.w;
    ((float4*)out)[i] = o;
}

// ---------------- launch ----------------------------------------------------
extern "C" void kernel_launch(void* const* d_in, const int* in_sizes, int n_in,
                              void* d_out, int out_size) {
    const float* x  = (const float*)d_in[0];
    const float* Wg = (const float*)d_in[1];
    const float* bg = (const float*)d_in[2];
    const float* W1 = (const float*)d_in[3];
    const float* b1 = (const float*)d_in[4];
    const float* W2 = (const float*)d_in[5];
    const float* b2 = (const float*)d_in[6];
    float* out = (float*)d_out;

    const int SMEM_BYTES =
        (TM * HS_STRIDE + TM * XS_STRIDE + TK * TNC) * 4 + TM * 12;  // 215296 B

    cudaFuncSetAttribute(expert_mlp_kernel,
                         cudaFuncAttributeMaxDynamicSharedMemorySize,
                         SMEM_BYTES);

    reset_kernel<<<1, 32>>>();
    gating_kernel<<<BATCH / 8, 256>>>(x, Wg, bg);
    scan_kernel<<<1, 32>>>();
    scatter_kernel<<<(BATCH * TOPK) / 256, 256>>>();
    expert_mlp_kernel<<<dim3(BATCH / TM, E_EXP), 256, SMEM_BYTES>>>(x, W1, b1, W2, b2);
    combine_kernel<<<(BATCH * (D_OUT / 4)) / 256, 256>>>(out);
}

// round 4
// speedup vs baseline: 2.2586x; 1.4062x over previous
#include <cuda_runtime.h>
#include <cuda_bf16.h>
#include <math.h>
#include <stdint.h>

typedef unsigned short u16;

#define E_EXP   16
#define TOPK    2
#define D_IN    256
#define D_H     512
#define D_OUT   256
#define BATCH   32768
#define NSLOT   (BATCH * TOPK)
#define TM      128

// ---------------- scratch (__device__ globals) ------------------------------
__device__ int   g_counts[E_EXP];
__device__ int   g_offsets[E_EXP + 1];
__device__ int   g_cursor[E_EXP];
__device__ int   g_topk_e[NSLOT];
__device__ float g_topk_w[NSLOT];
__device__ int   g_perm[NSLOT];
__device__ u16   g_xh [(size_t)BATCH * D_IN];        // x hi-bf16 plane
__device__ u16   g_xl [(size_t)BATCH * D_IN];        // x lo-bf16 plane
__device__ u16   g_w1h[(size_t)E_EXP * D_H * D_IN];  // W1^T [e][n][k] hi
__device__ u16   g_w1l[(size_t)E_EXP * D_H * D_IN];
__device__ u16   g_w2h[(size_t)E_EXP * D_OUT * D_H]; // W2^T [e][o][h] hi
__device__ u16   g_w2l[(size_t)E_EXP * D_OUT * D_H];
__device__ u16   g_hh [(size_t)NSLOT * D_H];         // H hi plane
__device__ u16   g_hl [(size_t)NSLOT * D_H];
__device__ float g_y  [(size_t)NSLOT * D_OUT];

// ---------------- helpers ---------------------------------------------------
__device__ __forceinline__ uint32_t smem_u32(const void* p) {
    uint32_t a;
    asm("{ .reg .u64 t; cvta.to.shared.u64 t, %1; cvt.u32.u64 %0, t; }" : "=r"(a) : "l"(p));
    return a;
}
__device__ __forceinline__ void cpa16(uint32_t dst, const void* src) {
    asm volatile("cp.async.cg.shared.global [%0], [%1], 16;" :: "r"(dst), "l"(src));
}
#define CP_COMMIT() asm volatile("cp.async.commit_group;" ::: "memory")
#define CP_WAIT0()  asm volatile("cp.async.wait_group 0;" ::: "memory")

__device__ __forceinline__ void mma_bf16(float c[4], const uint32_t a[4], const uint32_t b[2]) {
    asm volatile(
        "mma.sync.aligned.m16n8k16.row.col.f32.bf16.bf16.f32 "
        "{%0,%1,%2,%3}, {%4,%5,%6,%7}, {%8,%9}, {%0,%1,%2,%3};"
        : "+f"(c[0]), "+f"(c[1]), "+f"(c[2]), "+f"(c[3])
        : "r"(a[0]), "r"(a[1]), "r"(a[2]), "r"(a[3]), "r"(b[0]), "r"(b[1]));
}
__device__ __forceinline__ void split2(float v, u16& h, u16& l) {
    __nv_bfloat16 hb = __float2bfloat16(v);
    float r = v - __bfloat162float(hb);
    __nv_bfloat16 lb = __float2bfloat16(r);
    h = __bfloat16_as_ushort(hb);
    l = __bfloat16_as_ushort(lb);
}
__device__ __forceinline__ uint32_t lds32(const char* p) { return *(const uint32_t*)p; }

// ---------------- reset / gating / scan / scatter ---------------------------
__global__ void reset_kernel() {
    int i = threadIdx.x;
    if (i < E_EXP) g_counts[i] = 0;
}

__global__ void gating_kernel(const float* __restrict__ x,
                              const float* __restrict__ Wg,
                              const float* __restrict__ bg) {
    int warp = (blockIdx.x * blockDim.x + threadIdx.x) >> 5;
    int lane = threadIdx.x & 31;
    if (warp >= BATCH) return;
    const float* xr = x + (size_t)warp * D_IN;

    float acc[E_EXP];
#pragma unroll
    for (int e = 0; e < E_EXP; e++) acc[e] = 0.f;
#pragma unroll
    for (int i = 0; i < D_IN / 32; i++) {
        float xv = xr[i * 32 + lane];
        const float* wr = Wg + (size_t)(i * 32 + lane) * E_EXP;
#pragma unroll
        for (int e = 0; e < E_EXP; e++) acc[e] = fmaf(xv, wr[e], acc[e]);
    }
#pragma unroll
    for (int e = 0; e < E_EXP; e++) {
        float v = acc[e];
        v += __shfl_xor_sync(0xffffffffu, v, 16);
        v += __shfl_xor_sync(0xffffffffu, v, 8);
        v += __shfl_xor_sync(0xffffffffu, v, 4);
        v += __shfl_xor_sync(0xffffffffu, v, 2);
        v += __shfl_xor_sync(0xffffffffu, v, 1);
        acc[e] = v + bg[e];
    }
    if (lane == 0) {
        int i0 = 0; float v0 = acc[0];
#pragma unroll
        for (int e = 1; e < E_EXP; e++)
            if (acc[e] > v0) { v0 = acc[e]; i0 = e; }
        int i1 = -1; float v1 = -3.4e38f;
#pragma unroll
        for (int e = 0; e < E_EXP; e++)
            if (e != i0 && acc[e] > v1) { v1 = acc[e]; i1 = e; }
        float w0 = 1.f / (1.f + expf(v1 - v0));
        g_topk_e[warp * 2 + 0] = i0;
        g_topk_e[warp * 2 + 1] = i1;
        g_topk_w[warp * 2 + 0] = w0;
        g_topk_w[warp * 2 + 1] = 1.f - w0;
        atomicAdd(&g_counts[i0], 1);
        atomicAdd(&g_counts[i1], 1);
    }
}

__global__ void scan_kernel() {
    if (threadIdx.x == 0) {
        int s = 0;
        for (int e = 0; e < E_EXP; e++) {
            g_offsets[e] = s;
            g_cursor[e]  = s;
            s += g_counts[e];
        }
        g_offsets[E_EXP] = s;
    }
}

__global__ void scatter_kernel() {
    __shared__ int hist[E_EXP];
    __shared__ int base[E_EXP];
    int tid = threadIdx.x;
    if (tid < E_EXP) hist[tid] = 0;
    __syncthreads();
    int i = blockIdx.x * 256 + tid;
    int e = g_topk_e[i];
    int rank = atomicAdd(&hist[e], 1);
    __syncthreads();
    if (tid < E_EXP) base[tid] = atomicAdd(&g_cursor[tid], hist[tid]);
    __syncthreads();
    g_perm[base[e] + rank] = i;
}

// ---------------- prep: split planes ----------------------------------------
__global__ void pack_x_kernel(const float* __restrict__ x) {
    size_t i = (size_t)blockIdx.x * blockDim.x + threadIdx.x;   // per 4 elems
    float4 v = ((const float4*)x)[i];
    u16 h0, h1, h2, h3, l0, l1, l2, l3;
    split2(v.x, h0, l0); split2(v.y, h1, l1);
    split2(v.z, h2, l2); split2(v.w, h3, l3);
    ((uint2*)g_xh)[i] = make_uint2((uint32_t)h0 | ((uint32_t)h1 << 16),
                                   (uint32_t)h2 | ((uint32_t)h3 << 16));
    ((uint2*)g_xl)[i] = make_uint2((uint32_t)l0 | ((uint32_t)l1 << 16),
                                   (uint32_t)l2 | ((uint32_t)l3 << 16));
}

// in: [e][Kd][Nd] fp32  ->  hi/lo planes: [e][Nd][Kd] bf16
__global__ void pack_transpose_kernel(const float* __restrict__ in,
                                      int which, int Kd, int Nd) {
    u16* oh = which ? g_w2h : g_w1h;
    u16* ol = which ? g_w2l : g_w1l;
    __shared__ float t[32][33];
    int e  = blockIdx.z;
    int k0 = blockIdx.x * 32, n0 = blockIdx.y * 32;
    const float* ine = in + (size_t)e * Kd * Nd;
    u16* ohe = oh + (size_t)e * Kd * Nd;
    u16* ole = ol + (size_t)e * Kd * Nd;
    int tx = threadIdx.x, ty = threadIdx.y;      // (32, 8)
#pragma unroll
    for (int i = 0; i < 4; i++) {
        int k = k0 + ty + i * 8;
        t[ty + i * 8][tx] = ine[(size_t)k * Nd + n0 + tx];
    }
    __syncthreads();
#pragma unroll
    for (int i = 0; i < 4; i++) {
        int n = n0 + ty + i * 8;
        u16 h, l;
        split2(t[tx][ty + i * 8], h, l);
        ohe[(size_t)n * Kd + k0 + tx] = h;
        ole[(size_t)n * Kd + k0 + tx] = l;
    }
}

// ---------------- GEMM1: H = relu(X @ W1 + b1) ------------------------------
// smem (bytes): A hi [128][264 bf16] (528B rows), A lo, B double buffer
#define G1_AH   0
#define G1_AL   67584            // +128*528
#define G1_B0   135168           // buf b at +b*36864 (hi 18432 | lo 18432)
#define G1_BIAS 208896           // 512 floats
#define G1_SROW 210944           // 128 int
#define G1_SENT 211456           // 128 int
#define G1_SIZE 211968

__global__ void __launch_bounds__(256, 1)
gemm1_kernel(const float* __restrict__ b1) {
    int e = blockIdx.y, tile = blockIdx.x;
    int beg = g_offsets[e];
    int cnt = g_offsets[e + 1] - beg;
    int m0  = tile * TM;
    if (m0 >= cnt) return;

    extern __shared__ char sm[];
    uint32_t smb = smem_u32(sm);
    int tid  = threadIdx.x;
    int wid  = tid >> 5, lane = tid & 31;
    int warpM = wid >> 2, warpN = wid & 3;
    int lr = lane >> 2, lc2 = (lane & 3) * 2;

    int*   srow = (int*)(sm + G1_SROW);
    int*   sent = (int*)(sm + G1_SENT);
    float* bias = (float*)(sm + G1_BIAS);

    if (tid < TM) {
        int g = beg + m0 + tid;
        if (m0 + tid < cnt) {
            int entry = g_perm[g];
            srow[tid] = entry >> 1;
            sent[tid] = entry;
        } else {
            srow[tid] = 0;
            sent[tid] = -1;
        }
    }
    bias[tid]       = b1[e * D_H + tid];
    bias[tid + 256] = b1[e * D_H + tid + 256];
    __syncthreads();

    // ---- issue A gather (full 128x256, hi+lo) + B chunk 0 ----
    {
        int row = tid >> 1, half = tid & 1;
        size_t so = ((size_t)srow[row] * D_IN + half * 128) * 2;
        uint32_t dh = smb + G1_AH + row * 528 + half * 256;
        uint32_t dl = smb + G1_AL + row * 528 + half * 256;
#pragma unroll
        for (int i = 0; i < 16; i++) {
            cpa16(dh + i * 16, (const char*)g_xh + so + i * 16);
            cpa16(dl + i * 16, (const char*)g_xl + so + i * 16);
        }
    }
    const char* Wh = (const char*)g_w1h + (size_t)e * D_H * D_IN * 2;
    const char* Wl = (const char*)g_w1l + (size_t)e * D_H * D_IN * 2;
    {
        // B chunk it=0 (nc=0, kc=0) -> buf 0
        int r = tid >> 1, hf = tid & 1;
        size_t so = ((size_t)r * D_IN + hf * 32) * 2;
        uint32_t d = smb + G1_B0 + r * 144 + hf * 64;
#pragma unroll
        for (int i = 0; i < 4; i++) {
            cpa16(d + i * 16, Wh + so + i * 16);
            cpa16(d + 18432 + i * 16, Wl + so + i * 16);
        }
    }
    CP_COMMIT();

    float c[4][4][4];

    for (int it = 0; it < 16; it++) {
        int nc = it >> 2, kc = it & 3, buf = it & 1;
        CP_WAIT0();
        __syncthreads();
        if (it + 1 < 16) {      // issue next chunk into buf^1 (holds consumed it-1)
            int nn = (it + 1) >> 2, nk = (it + 1) & 3;
            int r = tid >> 1, hf = tid & 1;
            size_t so = ((size_t)(nn * 128 + r) * D_IN + nk * 64 + hf * 32) * 2;
            uint32_t d = smb + G1_B0 + (buf ^ 1) * 36864 + r * 144 + hf * 64;
#pragma unroll
            for (int i = 0; i < 4; i++) {
                cpa16(d + i * 16, Wh + so + i * 16);
                cpa16(d + 18432 + i * 16, Wl + so + i * 16);
            }
            CP_COMMIT();
        }
        if (kc == 0) {
#pragma unroll
            for (int mi = 0; mi < 4; mi++)
#pragma unroll
                for (int ni = 0; ni < 4; ni++)
#pragma unroll
                    for (int q = 0; q < 4; q++) c[mi][ni][q] = 0.f;
        }
        const char* Ah = sm + G1_AH;
        const char* Al = sm + G1_AL;
        const char* Bh = sm + G1_B0 + buf * 36864;
        const char* Bl = Bh + 18432;
#pragma unroll
        for (int k16 = 0; k16 < 4; k16++) {
            int ka = kc * 64 + k16 * 16 + lc2;
            int kb = k16 * 16 + lc2;
            uint32_t ah[4][4], al[4][4], bh[4][2], bl[4][2];
#pragma unroll
            for (int mi = 0; mi < 4; mi++) {
                int row = warpM * 64 + mi * 16 + lr;
                const char* p = Ah + row * 528 + ka * 2;
                ah[mi][0] = lds32(p);
                ah[mi][1] = lds32(p + 8 * 528);
                ah[mi][2] = lds32(p + 16);
                ah[mi][3] = lds32(p + 8 * 528 + 16);
                const char* q = Al + row * 528 + ka * 2;
                al[mi][0] = lds32(q);
                al[mi][1] = lds32(q + 8 * 528);
                al[mi][2] = lds32(q + 16);
                al[mi][3] = lds32(q + 8 * 528 + 16);
            }
#pragma unroll
            for (int ni = 0; ni < 4; ni++) {
                int n = warpN * 32 + ni * 8 + lr;
                const char* p = Bh + n * 144 + kb * 2;
                bh[ni][0] = lds32(p);
                bh[ni][1] = lds32(p + 16);
                const char* q = Bl + n * 144 + kb * 2;
                bl[ni][0] = lds32(q);
                bl[ni][1] = lds32(q + 16);
            }
#pragma unroll
            for (int mi = 0; mi < 4; mi++)
#pragma unroll
                for (int ni = 0; ni < 4; ni++) {
                    mma_bf16(c[mi][ni], ah[mi], bh[ni]);
                    mma_bf16(c[mi][ni], al[mi], bh[ni]);
                    mma_bf16(c[mi][ni], ah[mi], bl[ni]);
                }
        }
        if (kc == 3) {
            // epilogue for this nc: bias + relu + split -> g_hh / g_hl
#pragma unroll
            for (int mi = 0; mi < 4; mi++) {
                int r0 = warpM * 64 + mi * 16 + lr;
#pragma unroll
                for (int ni = 0; ni < 4; ni++) {
                    int n = nc * 128 + warpN * 32 + ni * 8 + lc2;
                    float b0 = bias[n], b1v = bias[n + 1];
#pragma unroll
                    for (int half = 0; half < 2; half++) {
                        int row = r0 + half * 8;
                        if (sent[row] >= 0) {
                            float v0 = c[mi][ni][half * 2 + 0] + b0;
                            float v1 = c[mi][ni][half * 2 + 1] + b1v;
                            v0 = v0 > 0.f ? v0 : 0.f;
                            v1 = v1 > 0.f ? v1 : 0.f;
                            u16 h0, l0, h1, l1;
                            split2(v0, h0, l0);
                            split2(v1, h1, l1);
                            size_t o = (size_t)(beg + m0 + row) * D_H + n;
                            *(uint32_t*)&g_hh[o] = (uint32_t)h0 | ((uint32_t)h1 << 16);
                            *(uint32_t*)&g_hl[o] = (uint32_t)l0 | ((uint32_t)l1 << 16);
                        }
                    }
                }
            }
        }
    }
}

// ---------------- GEMM2: y = w * (H @ W2 + b2) ------------------------------
// smem: double buffer of (A hi|A lo|B hi|B lo), each 18432 B ([128][72 bf16])
#define G2_BUF  0                // buf b at +b*73728
#define G2_BIAS 147456           // 256 floats
#define G2_SENT 148480           // 128 int
#define G2_SW   148992           // 128 float
#define G2_SIZE 149504

__global__ void __launch_bounds__(256, 1)
gemm2_kernel(const float* __restrict__ b2) {
    int e = blockIdx.y, tile = blockIdx.x;
    int beg = g_offsets[e];
    int cnt = g_offsets[e + 1] - beg;
    int m0  = tile * TM;
    if (m0 >= cnt) return;

    extern __shared__ char sm[];
    uint32_t smb = smem_u32(sm);
    int tid  = threadIdx.x;
    int wid  = tid >> 5, lane = tid & 31;
    int warpM = wid >> 2, warpN = wid & 3;
    int lr = lane >> 2, lc2 = (lane & 3) * 2;

    int*   sent = (int*)(sm + G2_SENT);
    float* swv  = (float*)(sm + G2_SW);
    float* bias = (float*)(sm + G2_BIAS);

    if (tid < TM) {
        int g = beg + m0 + tid;
        if (m0 + tid < cnt) {
            int entry = g_perm[g];
            sent[tid] = entry;
            swv[tid]  = g_topk_w[entry];
        } else {
            sent[tid] = -1;
            swv[tid]  = 0.f;
        }
    }
    if (tid < 256) bias[tid] = b2[e * D_OUT + tid];
    __syncthreads();

    const char* W2h = (const char*)g_w2h + (size_t)e * D_OUT * D_H * 2;
    const char* W2l = (const char*)g_w2l + (size_t)e * D_OUT * D_H * 2;

    int r  = tid >> 1, hf = tid & 1;
    int arow = (m0 + r < cnt) ? (beg + m0 + r) : beg;

    // issue chunk it=0
    {
        size_t sa = ((size_t)arow * D_H + hf * 32) * 2;
        size_t sb = ((size_t)r * D_H + hf * 32) * 2;
        uint32_t d = smb + r * 144 + hf * 64;
#pragma unroll
        for (int i = 0; i < 4; i++) {
            cpa16(d + i * 16,             (const char*)g_hh + sa + i * 16);
            cpa16(d + 18432 + i * 16,     (const char*)g_hl + sa + i * 16);
            cpa16(d + 36864 + i * 16,     W2h + sb + i * 16);
            cpa16(d + 55296 + i * 16,     W2l + sb + i * 16);
        }
    }
    CP_COMMIT();

    float c[4][4][4];

    for (int it = 0; it < 16; it++) {
        int nc = it >> 3, kc = it & 7, buf = it & 1;
        CP_WAIT0();
        __syncthreads();
        if (it + 1 < 16) {
            int nn = (it + 1) >> 3, nk = (it + 1) & 7;
            size_t sa = ((size_t)arow * D_H + nk * 64 + hf * 32) * 2;
            size_t sb = ((size_t)(nn * 128 + r) * D_H + nk * 64 + hf * 32) * 2;
            uint32_t d = smb + (buf ^ 1) * 73728 + r * 144 + hf * 64;
#pragma unroll
            for (int i = 0; i < 4; i++) {
                cpa16(d + i * 16,         (const char*)g_hh + sa + i * 16);
                cpa16(d + 18432 + i * 16, (const char*)g_hl + sa + i * 16);
                cpa16(d + 36864 + i * 16, W2h + sb + i * 16);
                cpa16(d + 55296 + i * 16, W2l + sb + i * 16);
            }
            CP_COMMIT();
        }
        if (kc == 0) {
#pragma unroll
            for (int mi = 0; mi < 4; mi++)
#pragma unroll
                for (int ni = 0; ni < 4; ni++)
#pragma unroll
                    for (int q = 0; q < 4; q++) c[mi][ni][q] = 0.f;
        }
        const char* Ah = sm + buf * 73728;
        const char* Al = Ah + 18432;
        const char* Bh = Ah + 36864;
        const char* Bl = Ah + 55296;
#pragma unroll
        for (int k16 = 0; k16 < 4; k16++) {
            int kb = k16 * 16 + lc2;
            uint32_t ah[4][4], al[4][4], bh[4][2], bl[4][2];
#pragma unroll
            for (int mi = 0; mi < 4; mi++) {
                int row = warpM * 64 + mi * 16 + lr;
                const char* p = Ah + row * 144 + kb * 2;
                ah[mi][0] = lds32(p);
                ah[mi][1] = lds32(p + 8 * 144);
                ah[mi][2] = lds32(p + 16);
                ah[mi][3] = lds32(p + 8 * 144 + 16);
                const char* q = Al + row * 144 + kb * 2;
                al[mi][0] = lds32(q);
                al[mi][1] = lds32(q + 8 * 144);
                al[mi][2] = lds32(q + 16);
                al[mi][3] = lds32(q + 8 * 144 + 16);
            }
#pragma unroll
            for (int ni = 0; ni < 4; ni++) {
                int n = warpN * 32 + ni * 8 + lr;
                const char* p = Bh + n * 144 + kb * 2;
                bh[ni][0] = lds32(p);
                bh[ni][1] = lds32(p + 16);
                const char* q = Bl + n * 144 + kb * 2;
                bl[ni][0] = lds32(q);
                bl[ni][1] = lds32(q + 16);
            }
#pragma unroll
            for (int mi = 0; mi < 4; mi++)
#pragma unroll
                for (int ni = 0; ni < 4; ni++) {
                    mma_bf16(c[mi][ni], ah[mi], bh[ni]);
                    mma_bf16(c[mi][ni], al[mi], bh[ni]);
                    mma_bf16(c[mi][ni], ah[mi], bl[ni]);
                }
        }
        if (kc == 7) {
#pragma unroll
            for (int mi = 0; mi < 4; mi++) {
                int r0 = warpM * 64 + mi * 16 + lr;
#pragma unroll
                for (int ni = 0; ni < 4; ni++) {
                    int n = nc * 128 + warpN * 32 + ni * 8 + lc2;
                    float b0 = bias[n], b1v = bias[n + 1];
#pragma unroll
                    for (int half = 0; half < 2; half++) {
                        int row = r0 + half * 8;
                        int entry = sent[row];
                        if (entry >= 0) {
                            float w = swv[row];
                            float2 o;
                            o.x = w * (c[mi][ni][half * 2 + 0] + b0);
                            o.y = w * (c[mi][ni][half * 2 + 1] + b1v);
                            *(float2*)&g_y[(size_t)entry * D_OUT + n] = o;
                        }
                    }
                }
            }
        }
    }
}

// ---------------- combine ---------------------------------------------------
__global__ void combine_kernel(float* __restrict__ out) {
    int i = blockIdx.x * blockDim.x + threadIdx.x;
    int b = i >> 6, q = i & 63;
    const float4* y4 = (const float4*)g_y;
    float4 u = y4[(size_t)(b * 2 + 0) * (D_OUT / 4) + q];
    float4 v = y4[(size_t)(b * 2 + 1) * (D_OUT / 4) + q];
    float4 o;
    o.x = u.x + v.x; o.y = u.y + v.y; o.z = u.z + v.z; o.w = u.w + v.w;
    ((float4*)out)[i] = o;
}

// ---------------- launch -----------------------------------------------------
extern "C" void kernel_launch(void* const* d_in, const int* in_sizes, int n_in,
                              void* d_out, int out_size) {
    const float* x  = (const float*)d_in[0];
    const float* Wg = (const float*)d_in[1];
    const float* bg = (const float*)d_in[2];
    const float* W1 = (const float*)d_in[3];
    const float* b1 = (const float*)d_in[4];
    const float* W2 = (const float*)d_in[5];
    const float* b2 = (const float*)d_in[6];
    float* out = (float*)d_out;

    cudaFuncSetAttribute(gemm1_kernel, cudaFuncAttributeMaxDynamicSharedMemorySize, G1_SIZE);
    cudaFuncSetAttribute(gemm2_kernel, cudaFuncAttributeMaxDynamicSharedMemorySize, G2_SIZE);

    reset_kernel<<<1, 32>>>();
    gating_kernel<<<BATCH / 8, 256>>>(x, Wg, bg);
    scan_kernel<<<1, 32>>>();
    scatter_kernel<<<NSLOT / 256, 256>>>();
    pack_x_kernel<<<(BATCH * D_IN / 4) / 256, 256>>>(x);
    pack_transpose_kernel<<<dim3(D_IN / 32, D_H / 32, E_EXP), dim3(32, 8)>>>(W1, 0, D_IN, D_H);
    pack_transpose_kernel<<<dim3(D_H / 32, D_OUT / 32, E_EXP), dim3(32, 8)>>>(W2, 1, D_H, D_OUT);
    gemm1_kernel<<<dim3(NSLOT / TM, E_EXP), 256, G1_SIZE>>>(b1);
    gemm2_kernel<<<dim3(NSLOT / TM, E_EXP), 256, G2_SIZE>>>(b2);
    combine_kernel<<<(BATCH * (D_OUT / 4)) / 256, 256>>>(out);
}

// round 5
// speedup vs baseline: 2.3028x; 1.0196x over previous
#include <cuda_runtime.h>
#include <cuda_bf16.h>
#include <math.h>
#include <stdint.h>

typedef unsigned short u16;

#define E_EXP   16
#define TOPK    2
#define D_IN    256
#define D_H     512
#define D_OUT   256
#define BATCH   32768
#define NSLOT   (BATCH * TOPK)
#define TM      128

// ---------------- scratch (__device__ globals) ------------------------------
__device__ int   g_counts[E_EXP];
__device__ int   g_offsets[E_EXP + 1];
__device__ int   g_cursor[E_EXP];
__device__ int   g_topk_e[NSLOT];
__device__ float g_topk_w[NSLOT];
__device__ int   g_perm[NSLOT];
__device__ u16   g_xh [(size_t)BATCH * D_IN];
__device__ u16   g_xl [(size_t)BATCH * D_IN];
__device__ u16   g_w1h[(size_t)E_EXP * D_H * D_IN];
__device__ u16   g_w1l[(size_t)E_EXP * D_H * D_IN];
__device__ u16   g_w2h[(size_t)E_EXP * D_OUT * D_H];
__device__ u16   g_w2l[(size_t)E_EXP * D_OUT * D_H];
__device__ u16   g_hh [(size_t)NSLOT * D_H];
__device__ u16   g_hl [(size_t)NSLOT * D_H];
__device__ float g_y  [(size_t)NSLOT * D_OUT];

// ---------------- helpers ---------------------------------------------------
__device__ __forceinline__ uint32_t smem_u32(const void* p) {
    uint32_t a;
    asm("{ .reg .u64 t; cvta.to.shared.u64 t, %1; cvt.u32.u64 %0, t; }" : "=r"(a) : "l"(p));
    return a;
}
__device__ __forceinline__ void cpa16(uint32_t dst, const void* src) {
    asm volatile("cp.async.cg.shared.global [%0], [%1], 16;" :: "r"(dst), "l"(src));
}
#define CP_COMMIT() asm volatile("cp.async.commit_group;" ::: "memory")
#define CP_WAIT0()  asm volatile("cp.async.wait_group 0;" ::: "memory")

__device__ __forceinline__ void mma_bf16(float c[4], const uint32_t a[4], const uint32_t b[2]) {
    asm volatile(
        "mma.sync.aligned.m16n8k16.row.col.f32.bf16.bf16.f32 "
        "{%0,%1,%2,%3}, {%4,%5,%6,%7}, {%8,%9}, {%0,%1,%2,%3};"
        : "+f"(c[0]), "+f"(c[1]), "+f"(c[2]), "+f"(c[3])
        : "r"(a[0]), "r"(a[1]), "r"(a[2]), "r"(a[3]), "r"(b[0]), "r"(b[1]));
}
__device__ __forceinline__ void ldsm_x4(uint32_t r[4], uint32_t addr) {
    asm volatile("ldmatrix.sync.aligned.m8n8.x4.shared.b16 {%0,%1,%2,%3}, [%4];"
        : "=r"(r[0]), "=r"(r[1]), "=r"(r[2]), "=r"(r[3]) : "r"(addr));
}
__device__ __forceinline__ void split2(float v, u16& h, u16& l) {
    __nv_bfloat16 hb = __float2bfloat16(v);
    float r = v - __bfloat162float(hb);
    __nv_bfloat16 lb = __float2bfloat16(r);
    h = __bfloat16_as_ushort(hb);
    l = __bfloat16_as_ushort(lb);
}

// ---------------- reset / gating / scan / scatter ---------------------------
__global__ void reset_kernel() {
    int i = threadIdx.x;
    if (i < E_EXP) g_counts[i] = 0;
}

__global__ void gating_kernel(const float* __restrict__ x,
                              const float* __restrict__ Wg,
                              const float* __restrict__ bg) {
    int warp = (blockIdx.x * blockDim.x + threadIdx.x) >> 5;
    int lane = threadIdx.x & 31;
    if (warp >= BATCH) return;
    const float* xr = x + (size_t)warp * D_IN;

    float acc[E_EXP];
#pragma unroll
    for (int e = 0; e < E_EXP; e++) acc[e] = 0.f;
#pragma unroll
    for (int i = 0; i < D_IN / 32; i++) {
        float xv = xr[i * 32 + lane];
        const float* wr = Wg + (size_t)(i * 32 + lane) * E_EXP;
#pragma unroll
        for (int e = 0; e < E_EXP; e++) acc[e] = fmaf(xv, wr[e], acc[e]);
    }
#pragma unroll
    for (int e = 0; e < E_EXP; e++) {
        float v = acc[e];
        v += __shfl_xor_sync(0xffffffffu, v, 16);
        v += __shfl_xor_sync(0xffffffffu, v, 8);
        v += __shfl_xor_sync(0xffffffffu, v, 4);
        v += __shfl_xor_sync(0xffffffffu, v, 2);
        v += __shfl_xor_sync(0xffffffffu, v, 1);
        acc[e] = v + bg[e];
    }
    if (lane == 0) {
        int i0 = 0; float v0 = acc[0];
#pragma unroll
        for (int e = 1; e < E_EXP; e++)
            if (acc[e] > v0) { v0 = acc[e]; i0 = e; }
        int i1 = -1; float v1 = -3.4e38f;
#pragma unroll
        for (int e = 0; e < E_EXP; e++)
            if (e != i0 && acc[e] > v1) { v1 = acc[e]; i1 = e; }
        float w0 = 1.f / (1.f + expf(v1 - v0));
        g_topk_e[warp * 2 + 0] = i0;
        g_topk_e[warp * 2 + 1] = i1;
        g_topk_w[warp * 2 + 0] = w0;
        g_topk_w[warp * 2 + 1] = 1.f - w0;
        atomicAdd(&g_counts[i0], 1);
        atomicAdd(&g_counts[i1], 1);
    }
}

__global__ void scan_kernel() {
    if (threadIdx.x == 0) {
        int s = 0;
        for (int e = 0; e < E_EXP; e++) {
            g_offsets[e] = s;
            g_cursor[e]  = s;
            s += g_counts[e];
        }
        g_offsets[E_EXP] = s;
    }
}

__global__ void scatter_kernel() {
    __shared__ int hist[E_EXP];
    __shared__ int base[E_EXP];
    int tid = threadIdx.x;
    if (tid < E_EXP) hist[tid] = 0;
    __syncthreads();
    int i = blockIdx.x * 256 + tid;
    int e = g_topk_e[i];
    int rank = atomicAdd(&hist[e], 1);
    __syncthreads();
    if (tid < E_EXP) base[tid] = atomicAdd(&g_cursor[tid], hist[tid]);
    __syncthreads();
    g_perm[base[e] + rank] = i;
}

// ---------------- prep: split planes ----------------------------------------
__global__ void pack_x_kernel(const float* __restrict__ x) {
    size_t i = (size_t)blockIdx.x * blockDim.x + threadIdx.x;
    float4 v = ((const float4*)x)[i];
    u16 h0, h1, h2, h3, l0, l1, l2, l3;
    split2(v.x, h0, l0); split2(v.y, h1, l1);
    split2(v.z, h2, l2); split2(v.w, h3, l3);
    ((uint2*)g_xh)[i] = make_uint2((uint32_t)h0 | ((uint32_t)h1 << 16),
                                   (uint32_t)h2 | ((uint32_t)h3 << 16));
    ((uint2*)g_xl)[i] = make_uint2((uint32_t)l0 | ((uint32_t)l1 << 16),
                                   (uint32_t)l2 | ((uint32_t)l3 << 16));
}

__global__ void pack_transpose_kernel(const float* __restrict__ in,
                                      int which, int Kd, int Nd) {
    u16* oh = which ? g_w2h : g_w1h;
    u16* ol = which ? g_w2l : g_w1l;
    __shared__ float t[32][33];
    int e  = blockIdx.z;
    int k0 = blockIdx.x * 32, n0 = blockIdx.y * 32;
    const float* ine = in + (size_t)e * Kd * Nd;
    u16* ohe = oh + (size_t)e * Kd * Nd;
    u16* ole = ol + (size_t)e * Kd * Nd;
    int tx = threadIdx.x, ty = threadIdx.y;
#pragma unroll
    for (int i = 0; i < 4; i++) {
        int k = k0 + ty + i * 8;
        t[ty + i * 8][tx] = ine[(size_t)k * Nd + n0 + tx];
    }
    __syncthreads();
#pragma unroll
    for (int i = 0; i < 4; i++) {
        int n = n0 + ty + i * 8;
        u16 h, l;
        split2(t[tx][ty + i * 8], h, l);
        ohe[(size_t)n * Kd + k0 + tx] = h;
        ole[(size_t)n * Kd + k0 + tx] = l;
    }
}

// ---------------- GEMM1: H = relu(X @ W1 + b1) ------------------------------
#define G1_AH   0
#define G1_AL   67584            // +128*528
#define G1_B0   135168           // buf b at +b*36864 (hi 18432 | lo 18432)
#define G1_BIAS 208896
#define G1_SROW 210944
#define G1_SENT 211456
#define G1_SIZE 211968

__global__ void __launch_bounds__(256, 1)
gemm1_kernel(const float* __restrict__ b1) {
    int e = blockIdx.y, tile = blockIdx.x;
    int beg = g_offsets[e];
    int cnt = g_offsets[e + 1] - beg;
    int m0  = tile * TM;
    if (m0 >= cnt) return;

    extern __shared__ char sm[];
    uint32_t smb = smem_u32(sm);
    int tid  = threadIdx.x;
    int wid  = tid >> 5, lane = tid & 31;
    int warpM = wid >> 2, warpN = wid & 3;
    int lr = lane >> 2, lc2 = (lane & 3) * 2;

    int*   srow = (int*)(sm + G1_SROW);
    int*   sent = (int*)(sm + G1_SENT);
    float* bias = (float*)(sm + G1_BIAS);

    if (tid < TM) {
        int g = beg + m0 + tid;
        if (m0 + tid < cnt) {
            int entry = g_perm[g];
            srow[tid] = entry >> 1;
            sent[tid] = entry;
        } else {
            srow[tid] = 0;
            sent[tid] = -1;
        }
    }
    bias[tid]       = b1[e * D_H + tid];
    bias[tid + 256] = b1[e * D_H + tid + 256];
    __syncthreads();

    // ---- A gather (full 128x256 hi+lo) + B chunk 0 ----
    {
        int row = tid >> 1, half = tid & 1;
        size_t so = ((size_t)srow[row] * D_IN + half * 128) * 2;
        uint32_t dh = smb + G1_AH + row * 528 + half * 256;
        uint32_t dl = smb + G1_AL + row * 528 + half * 256;
#pragma unroll
        for (int i = 0; i < 16; i++) {
            cpa16(dh + i * 16, (const char*)g_xh + so + i * 16);
            cpa16(dl + i * 16, (const char*)g_xl + so + i * 16);
        }
    }
    const char* Wh = (const char*)g_w1h + (size_t)e * D_H * D_IN * 2;
    const char* Wl = (const char*)g_w1l + (size_t)e * D_H * D_IN * 2;
    {
        int r = tid >> 1, hf = tid & 1;
        size_t so = ((size_t)r * D_IN + hf * 32) * 2;
        uint32_t d = smb + G1_B0 + r * 144 + hf * 64;
#pragma unroll
        for (int i = 0; i < 4; i++) {
            cpa16(d + i * 16, Wh + so + i * 16);
            cpa16(d + 18432 + i * 16, Wl + so + i * 16);
        }
    }
    CP_COMMIT();

    // ldmatrix lane-address components
    uint32_t aoff = (uint32_t)(warpM * 64 + (lane & 15)) * 528 + ((lane >> 4) << 4);
    uint32_t boff = (uint32_t)(warpN * 32 + (lane & 7) + (((lane >> 4) & 1) << 3)) * 144
                  + (((lane >> 3) & 1) << 4);

    float c[4][4][4];

    for (int it = 0; it < 16; it++) {
        int nc = it >> 2, kc = it & 3, buf = it & 1;
        CP_WAIT0();
        __syncthreads();
        if (it + 1 < 16) {
            int nn = (it + 1) >> 2, nk = (it + 1) & 3;
            int r = tid >> 1, hf = tid & 1;
            size_t so = ((size_t)(nn * 128 + r) * D_IN + nk * 64 + hf * 32) * 2;
            uint32_t d = smb + G1_B0 + (buf ^ 1) * 36864 + r * 144 + hf * 64;
#pragma unroll
            for (int i = 0; i < 4; i++) {
                cpa16(d + i * 16, Wh + so + i * 16);
                cpa16(d + 18432 + i * 16, Wl + so + i * 16);
            }
            CP_COMMIT();
        }
        if (kc == 0) {
#pragma unroll
            for (int mi = 0; mi < 4; mi++)
#pragma unroll
                for (int ni = 0; ni < 4; ni++)
#pragma unroll
                    for (int q = 0; q < 4; q++) c[mi][ni][q] = 0.f;
        }
        uint32_t aBaseH = smb + G1_AH + aoff + kc * 128;   // kc*64 elems * 2B
        uint32_t aBaseL = smb + G1_AL + aoff + kc * 128;
        uint32_t bBaseH = smb + G1_B0 + buf * 36864 + boff;
        uint32_t bBaseL = bBaseH + 18432;
#pragma unroll
        for (int k16 = 0; k16 < 4; k16++) {
            uint32_t ah[4][4], al[4][4], bh[4][2], bl[4][2];
#pragma unroll
            for (int mi = 0; mi < 4; mi++) {
                ldsm_x4(ah[mi], aBaseH + mi * 8448 + k16 * 32);
                ldsm_x4(al[mi], aBaseL + mi * 8448 + k16 * 32);
            }
#pragma unroll
            for (int p = 0; p < 2; p++) {
                uint32_t r4[4];
                ldsm_x4(r4, bBaseH + p * 2304 + k16 * 32);
                bh[2 * p][0] = r4[0]; bh[2 * p][1] = r4[1];
                bh[2 * p + 1][0] = r4[2]; bh[2 * p + 1][1] = r4[3];
                ldsm_x4(r4, bBaseL + p * 2304 + k16 * 32);
                bl[2 * p][0] = r4[0]; bl[2 * p][1] = r4[1];
                bl[2 * p + 1][0] = r4[2]; bl[2 * p + 1][1] = r4[3];
            }
            // term-major order: dependent MMAs on same accumulator are 16 apart
#pragma unroll
            for (int mi = 0; mi < 4; mi++)
#pragma unroll
                for (int ni = 0; ni < 4; ni++) mma_bf16(c[mi][ni], ah[mi], bh[ni]);
#pragma unroll
            for (int mi = 0; mi < 4; mi++)
#pragma unroll
                for (int ni = 0; ni < 4; ni++) mma_bf16(c[mi][ni], al[mi], bh[ni]);
#pragma unroll
            for (int mi = 0; mi < 4; mi++)
#pragma unroll
                for (int ni = 0; ni < 4; ni++) mma_bf16(c[mi][ni], ah[mi], bl[ni]);
        }
        if (kc == 3) {
#pragma unroll
            for (int mi = 0; mi < 4; mi++) {
                int r0 = warpM * 64 + mi * 16 + lr;
#pragma unroll
                for (int ni = 0; ni < 4; ni++) {
                    int n = nc * 128 + warpN * 32 + ni * 8 + lc2;
                    float b0 = bias[n], b1v = bias[n + 1];
#pragma unroll
                    for (int half = 0; half < 2; half++) {
                        int row = r0 + half * 8;
                        if (sent[row] >= 0) {
                            float v0 = c[mi][ni][half * 2 + 0] + b0;
                            float v1 = c[mi][ni][half * 2 + 1] + b1v;
                            v0 = v0 > 0.f ? v0 : 0.f;
                            v1 = v1 > 0.f ? v1 : 0.f;
                            u16 h0, l0, h1, l1;
                            split2(v0, h0, l0);
                            split2(v1, h1, l1);
                            size_t o = (size_t)(beg + m0 + row) * D_H + n;
                            *(uint32_t*)&g_hh[o] = (uint32_t)h0 | ((uint32_t)h1 << 16);
                            *(uint32_t*)&g_hl[o] = (uint32_t)l0 | ((uint32_t)l1 << 16);
                        }
                    }
                }
            }
        }
    }
}

// ---------------- GEMM2: y = w * (H @ W2 + b2) ------------------------------
#define G2_BUF  0                // buf b at +b*73728 (Ah|Al|Bh|Bl 18432 each)
#define G2_BIAS 147456
#define G2_SENT 148480
#define G2_SW   148992
#define G2_SIZE 149504

__global__ void __launch_bounds__(256, 1)
gemm2_kernel(const float* __restrict__ b2) {
    int e = blockIdx.y, tile = blockIdx.x;
    int beg = g_offsets[e];
    int cnt = g_offsets[e + 1] - beg;
    int m0  = tile * TM;
    if (m0 >= cnt) return;

    extern __shared__ char sm[];
    uint32_t smb = smem_u32(sm);
    int tid  = threadIdx.x;
    int wid  = tid >> 5, lane = tid & 31;
    int warpM = wid >> 2, warpN = wid & 3;
    int lr = lane >> 2, lc2 = (lane & 3) * 2;

    int*   sent = (int*)(sm + G2_SENT);
    float* swv  = (float*)(sm + G2_SW);
    float* bias = (float*)(sm + G2_BIAS);

    if (tid < TM) {
        int g = beg + m0 + tid;
        if (m0 + tid < cnt) {
            int entry = g_perm[g];
            sent[tid] = entry;
            swv[tid]  = g_topk_w[entry];
        } else {
            sent[tid] = -1;
            swv[tid]  = 0.f;
        }
    }
    if (tid < 256) bias[tid] = b2[e * D_OUT + tid];
    __syncthreads();

    const char* W2h = (const char*)g_w2h + (size_t)e * D_OUT * D_H * 2;
    const char* W2l = (const char*)g_w2l + (size_t)e * D_OUT * D_H * 2;

    int r  = tid >> 1, hf = tid & 1;
    int arow = (m0 + r < cnt) ? (beg + m0 + r) : beg;

    {
        size_t sa = ((size_t)arow * D_H + hf * 32) * 2;
        size_t sb = ((size_t)r * D_H + hf * 32) * 2;
        uint32_t d = smb + r * 144 + hf * 64;
#pragma unroll
        for (int i = 0; i < 4; i++) {
            cpa16(d + i * 16,         (const char*)g_hh + sa + i * 16);
            cpa16(d + 18432 + i * 16, (const char*)g_hl + sa + i * 16);
            cpa16(d + 36864 + i * 16, W2h + sb + i * 16);
            cpa16(d + 55296 + i * 16, W2l + sb + i * 16);
        }
    }
    CP_COMMIT();

    uint32_t aoff = (uint32_t)(warpM * 64 + (lane & 15)) * 144 + ((lane >> 4) << 4);
    uint32_t boff = (uint32_t)(warpN * 32 + (lane & 7) + (((lane >> 4) & 1) << 3)) * 144
                  + (((lane >> 3) & 1) << 4);

    float c[4][4][4];

    for (int it = 0; it < 16; it++) {
        int nc = it >> 3, kc = it & 7, buf = it & 1;
        CP_WAIT0();
        __syncthreads();
        if (it + 1 < 16) {
            int nn = (it + 1) >> 3, nk = (it + 1) & 7;
            size_t sa = ((size_t)arow * D_H + nk * 64 + hf * 32) * 2;
            size_t sb = ((size_t)(nn * 128 + r) * D_H + nk * 64 + hf * 32) * 2;
            uint32_t d = smb + (buf ^ 1) * 73728 + r * 144 + hf * 64;
#pragma unroll
            for (int i = 0; i < 4; i++) {
                cpa16(d + i * 16,         (const char*)g_hh + sa + i * 16);
                cpa16(d + 18432 + i * 16, (const char*)g_hl + sa + i * 16);
                cpa16(d + 36864 + i * 16, W2h + sb + i * 16);
                cpa16(d + 55296 + i * 16, W2l + sb + i * 16);
            }
            CP_COMMIT();
        }
        if (kc == 0) {
#pragma unroll
            for (int mi = 0; mi < 4; mi++)
#pragma unroll
                for (int ni = 0; ni < 4; ni++)
#pragma unroll
                    for (int q = 0; q < 4; q++) c[mi][ni][q] = 0.f;
        }
        uint32_t base  = smb + buf * 73728;
        uint32_t aBaseH = base + aoff;
        uint32_t aBaseL = aBaseH + 18432;
        uint32_t bBaseH = base + 36864 + boff;
        uint32_t bBaseL = bBaseH + 18432;
#pragma unroll
        for (int k16 = 0; k16 < 4; k16++) {
            uint32_t ah[4][4], al[4][4], bh[4][2], bl[4][2];
#pragma unroll
            for (int mi = 0; mi < 4; mi++) {
                ldsm_x4(ah[mi], aBaseH + mi * 2304 + k16 * 32);
                ldsm_x4(al[mi], aBaseL + mi * 2304 + k16 * 32);
            }
#pragma unroll
            for (int p = 0; p < 2; p++) {
                uint32_t r4[4];
                ldsm_x4(r4, bBaseH + p * 2304 + k16 * 32);
                bh[2 * p][0] = r4[0]; bh[2 * p][1] = r4[1];
                bh[2 * p + 1][0] = r4[2]; bh[2 * p + 1][1] = r4[3];
                ldsm_x4(r4, bBaseL + p * 2304 + k16 * 32);
                bl[2 * p][0] = r4[0]; bl[2 * p][1] = r4[1];
                bl[2 * p + 1][0] = r4[2]; bl[2 * p + 1][1] = r4[3];
            }
#pragma unroll
            for (int mi = 0; mi < 4; mi++)
#pragma unroll
                for (int ni = 0; ni < 4; ni++) mma_bf16(c[mi][ni], ah[mi], bh[ni]);
#pragma unroll
            for (int mi = 0; mi < 4; mi++)
#pragma unroll
                for (int ni = 0; ni < 4; ni++) mma_bf16(c[mi][ni], al[mi], bh[ni]);
#pragma unroll
            for (int mi = 0; mi < 4; mi++)
#pragma unroll
                for (int ni = 0; ni < 4; ni++) mma_bf16(c[mi][ni], ah[mi], bl[ni]);
        }
        if (kc == 7) {
#pragma unroll
            for (int mi = 0; mi < 4; mi++) {
                int r0 = warpM * 64 + mi * 16 + lr;
#pragma unroll
                for (int ni = 0; ni < 4; ni++) {
                    int n = nc * 128 + warpN * 32 + ni * 8 + lc2;
                    float b0 = bias[n], b1v = bias[n + 1];
#pragma unroll
                    for (int half = 0; half < 2; half++) {
                        int row = r0 + half * 8;
                        int entry = sent[row];
                        if (entry >= 0) {
                            float w = swv[row];
                            float2 o;
                            o.x = w * (c[mi][ni][half * 2 + 0] + b0);
                            o.y = w * (c[mi][ni][half * 2 + 1] + b1v);
                            *(float2*)&g_y[(size_t)entry * D_OUT + n] = o;
                        }
                    }
                }
            }
        }
    }
}

// ---------------- combine ---------------------------------------------------
__global__ void combine_kernel(float* __restrict__ out) {
    int i = blockIdx.x * blockDim.x + threadIdx.x;
    int b = i >> 6, q = i & 63;
    const float4* y4 = (const float4*)g_y;
    float4 u = y4[(size_t)(b * 2 + 0) * (D_OUT / 4) + q];
    float4 v = y4[(size_t)(b * 2 + 1) * (D_OUT / 4) + q];
    float4 o;
    o.x = u.x + v.x; o.y = u.y + v.y; o.z = u.z + v.z; o.w = u.w + v.w;
    ((float4*)out)[i] = o;
}

// ---------------- launch -----------------------------------------------------
extern "C" void kernel_launch(void* const* d_in, const int* in_sizes, int n_in,
                              void* d_out, int out_size) {
    const float* x  = (const float*)d_in[0];
    const float* Wg = (const float*)d_in[1];
    const float* bg = (const float*)d_in[2];
    const float* W1 = (const float*)d_in[3];
    const float* b1 = (const float*)d_in[4];
    const float* W2 = (const float*)d_in[5];
    const float* b2 = (const float*)d_in[6];
    float* out = (float*)d_out;

    cudaFuncSetAttribute(gemm1_kernel, cudaFuncAttributeMaxDynamicSharedMemorySize, G1_SIZE);
    cudaFuncSetAttribute(gemm2_kernel, cudaFuncAttributeMaxDynamicSharedMemorySize, G2_SIZE);

    reset_kernel<<<1, 32>>>();
    gating_kernel<<<BATCH / 8, 256>>>(x, Wg, bg);
    scan_kernel<<<1, 32>>>();
    scatter_kernel<<<NSLOT / 256, 256>>>();
    pack_x_kernel<<<(BATCH * D_IN / 4) / 256, 256>>>(x);
    pack_transpose_kernel<<<dim3(D_IN / 32, D_H / 32, E_EXP), dim3(32, 8)>>>(W1, 0, D_IN, D_H);
    pack_transpose_kernel<<<dim3(D_H / 32, D_OUT / 32, E_EXP), dim3(32, 8)>>>(W2, 1, D_H, D_OUT);
    gemm1_kernel<<<dim3(NSLOT / TM, E_EXP), 256, G1_SIZE>>>(b1);
    gemm2_kernel<<<dim3(NSLOT / TM, E_EXP), 256, G2_SIZE>>>(b2);
    combine_kernel<<<(BATCH * (D_OUT / 4)) / 256, 256>>>(out);
}

// round 6
// speedup vs baseline: 2.5143x; 1.0919x over previous
#include <cuda_runtime.h>
#include <cuda_bf16.h>
#include <math.h>
#include <stdint.h>

typedef unsigned short u16;

#define E_EXP   16
#define TOPK    2
#define D_IN    256
#define D_H     512
#define D_OUT   256
#define BATCH   32768
#define NSLOT   (BATCH * TOPK)
#define TM      128

#define RSTRIDE 80               // padded smem row stride (bytes) for 64B K-chunk rows
#define PLANE   (128 * RSTRIDE)  // 10240 B
#define STAGE   (4 * PLANE)      // Ah|Al|Bh|Bl = 40960 B

// ---------------- scratch (__device__ globals) ------------------------------
__device__ int   g_counts[E_EXP];
__device__ int   g_offsets[E_EXP + 1];
__device__ int   g_cursor[E_EXP];
__device__ int   g_topk_e[NSLOT];
__device__ float g_topk_w[NSLOT];
__device__ int   g_perm[NSLOT];
__device__ u16   g_xh [(size_t)BATCH * D_IN];
__device__ u16   g_xl [(size_t)BATCH * D_IN];
__device__ u16   g_w1h[(size_t)E_EXP * D_H * D_IN];
__device__ u16   g_w1l[(size_t)E_EXP * D_H * D_IN];
__device__ u16   g_w2h[(size_t)E_EXP * D_OUT * D_H];
__device__ u16   g_w2l[(size_t)E_EXP * D_OUT * D_H];
__device__ u16   g_hh [(size_t)NSLOT * D_H];
__device__ u16   g_hl [(size_t)NSLOT * D_H];
__device__ float g_y  [(size_t)NSLOT * D_OUT];

// ---------------- helpers ---------------------------------------------------
__device__ __forceinline__ uint32_t smem_u32(const void* p) {
    uint32_t a;
    asm("{ .reg .u64 t; cvta.to.shared.u64 t, %1; cvt.u32.u64 %0, t; }" : "=r"(a) : "l"(p));
    return a;
}
__device__ __forceinline__ void cpa16(uint32_t dst, const void* src) {
    asm volatile("cp.async.cg.shared.global [%0], [%1], 16;" :: "r"(dst), "l"(src));
}
#define CP_COMMIT() asm volatile("cp.async.commit_group;" ::: "memory")
#define CP_WAIT0()  asm volatile("cp.async.wait_group 0;" ::: "memory")

__device__ __forceinline__ void mma_bf16(float c[4], const uint32_t a[4], const uint32_t b[2]) {
    asm volatile(
        "mma.sync.aligned.m16n8k16.row.col.f32.bf16.bf16.f32 "
        "{%0,%1,%2,%3}, {%4,%5,%6,%7}, {%8,%9}, {%0,%1,%2,%3};"
        : "+f"(c[0]), "+f"(c[1]), "+f"(c[2]), "+f"(c[3])
        : "r"(a[0]), "r"(a[1]), "r"(a[2]), "r"(a[3]), "r"(b[0]), "r"(b[1]));
}
__device__ __forceinline__ void ldsm_x4(uint32_t r[4], uint32_t addr) {
    asm volatile("ldmatrix.sync.aligned.m8n8.x4.shared.b16 {%0,%1,%2,%3}, [%4];"
        : "=r"(r[0]), "=r"(r[1]), "=r"(r[2]), "=r"(r[3]) : "r"(addr));
}
__device__ __forceinline__ void split2(float v, u16& h, u16& l) {
    __nv_bfloat16 hb = __float2bfloat16(v);
    float r = v - __bfloat162float(hb);
    __nv_bfloat16 lb = __float2bfloat16(r);
    h = __bfloat16_as_ushort(hb);
    l = __bfloat16_as_ushort(lb);
}

// ---------------- reset / gating / scan / scatter ---------------------------
__global__ void reset_kernel() {
    int i = threadIdx.x;
    if (i < E_EXP) g_counts[i] = 0;
}

__global__ void gating_kernel(const float* __restrict__ x,
                              const float* __restrict__ Wg,
                              const float* __restrict__ bg) {
    int warp = (blockIdx.x * blockDim.x + threadIdx.x) >> 5;
    int lane = threadIdx.x & 31;
    if (warp >= BATCH) return;
    const float* xr = x + (size_t)warp * D_IN;

    float acc[E_EXP];
#pragma unroll
    for (int e = 0; e < E_EXP; e++) acc[e] = 0.f;
#pragma unroll
    for (int i = 0; i < D_IN / 32; i++) {
        float xv = xr[i * 32 + lane];
        const float* wr = Wg + (size_t)(i * 32 + lane) * E_EXP;
#pragma unroll
        for (int e = 0; e < E_EXP; e++) acc[e] = fmaf(xv, wr[e], acc[e]);
    }
#pragma unroll
    for (int e = 0; e < E_EXP; e++) {
        float v = acc[e];
        v += __shfl_xor_sync(0xffffffffu, v, 16);
        v += __shfl_xor_sync(0xffffffffu, v, 8);
        v += __shfl_xor_sync(0xffffffffu, v, 4);
        v += __shfl_xor_sync(0xffffffffu, v, 2);
        v += __shfl_xor_sync(0xffffffffu, v, 1);
        acc[e] = v + bg[e];
    }
    if (lane == 0) {
        int i0 = 0; float v0 = acc[0];
#pragma unroll
        for (int e = 1; e < E_EXP; e++)
            if (acc[e] > v0) { v0 = acc[e]; i0 = e; }
        int i1 = -1; float v1 = -3.4e38f;
#pragma unroll
        for (int e = 0; e < E_EXP; e++)
            if (e != i0 && acc[e] > v1) { v1 = acc[e]; i1 = e; }
        float w0 = 1.f / (1.f + expf(v1 - v0));
        g_topk_e[warp * 2 + 0] = i0;
        g_topk_e[warp * 2 + 1] = i1;
        g_topk_w[warp * 2 + 0] = w0;
        g_topk_w[warp * 2 + 1] = 1.f - w0;
        atomicAdd(&g_counts[i0], 1);
        atomicAdd(&g_counts[i1], 1);
    }
}

__global__ void scan_kernel() {
    if (threadIdx.x == 0) {
        int s = 0;
        for (int e = 0; e < E_EXP; e++) {
            g_offsets[e] = s;
            g_cursor[e]  = s;
            s += g_counts[e];
        }
        g_offsets[E_EXP] = s;
    }
}

__global__ void scatter_kernel() {
    __shared__ int hist[E_EXP];
    __shared__ int base[E_EXP];
    int tid = threadIdx.x;
    if (tid < E_EXP) hist[tid] = 0;
    __syncthreads();
    int i = blockIdx.x * 256 + tid;
    int e = g_topk_e[i];
    int rank = atomicAdd(&hist[e], 1);
    __syncthreads();
    if (tid < E_EXP) base[tid] = atomicAdd(&g_cursor[tid], hist[tid]);
    __syncthreads();
    g_perm[base[e] + rank] = i;
}

// ---------------- prep: split planes ----------------------------------------
__global__ void pack_x_kernel(const float* __restrict__ x) {
    size_t i = (size_t)blockIdx.x * blockDim.x + threadIdx.x;
    float4 v = ((const float4*)x)[i];
    u16 h0, h1, h2, h3, l0, l1, l2, l3;
    split2(v.x, h0, l0); split2(v.y, h1, l1);
    split2(v.z, h2, l2); split2(v.w, h3, l3);
    ((uint2*)g_xh)[i] = make_uint2((uint32_t)h0 | ((uint32_t)h1 << 16),
                                   (uint32_t)h2 | ((uint32_t)h3 << 16));
    ((uint2*)g_xl)[i] = make_uint2((uint32_t)l0 | ((uint32_t)l1 << 16),
                                   (uint32_t)l2 | ((uint32_t)l3 << 16));
}

__global__ void pack_transpose_kernel(const float* __restrict__ in,
                                      int which, int Kd, int Nd) {
    u16* oh = which ? g_w2h : g_w1h;
    u16* ol = which ? g_w2l : g_w1l;
    __shared__ float t[32][33];
    int e  = blockIdx.z;
    int k0 = blockIdx.x * 32, n0 = blockIdx.y * 32;
    const float* ine = in + (size_t)e * Kd * Nd;
    u16* ohe = oh + (size_t)e * Kd * Nd;
    u16* ole = ol + (size_t)e * Kd * Nd;
    int tx = threadIdx.x, ty = threadIdx.y;
#pragma unroll
    for (int i = 0; i < 4; i++) {
        int k = k0 + ty + i * 8;
        t[ty + i * 8][tx] = ine[(size_t)k * Nd + n0 + tx];
    }
    __syncthreads();
#pragma unroll
    for (int i = 0; i < 4; i++) {
        int n = n0 + ty + i * 8;
        u16 h, l;
        split2(t[tx][ty + i * 8], h, l);
        ohe[(size_t)n * Kd + k0 + tx] = h;
        ole[(size_t)n * Kd + k0 + tx] = l;
    }
}

// ---------------- GEMM1: H = relu(X @ W1 + b1), occ-2 streaming -------------
// smem: 2 stages x (Ah|Al|Bh|Bl), K-chunk 32, 80B padded rows
#define G1_BIAS (2 * STAGE)          // 81920: 512 floats
#define G1_SROW (G1_BIAS + 2048)     // 83968: 128 int
#define G1_SENT (G1_SROW + 512)      // 84480
#define G1_SIZE (G1_SENT + 512)      // 84992

__global__ void __launch_bounds__(256, 2)
gemm1_kernel(const float* __restrict__ b1) {
    int e = blockIdx.y, tile = blockIdx.x;
    int beg = g_offsets[e];
    int cnt = g_offsets[e + 1] - beg;
    int m0  = tile * TM;
    if (m0 >= cnt) return;

    extern __shared__ char sm[];
    uint32_t smb = smem_u32(sm);
    int tid  = threadIdx.x;
    int wid  = tid >> 5, lane = tid & 31;
    int warpM = wid >> 2, warpN = wid & 3;
    int lr = lane >> 2, lc2 = (lane & 3) * 2;

    int*   srow = (int*)(sm + G1_SROW);
    int*   sent = (int*)(sm + G1_SENT);
    float* bias = (float*)(sm + G1_BIAS);

    if (tid < TM) {
        int g = beg + m0 + tid;
        if (m0 + tid < cnt) {
            int entry = g_perm[g];
            srow[tid] = entry >> 1;
            sent[tid] = entry;
        } else {
            srow[tid] = 0;
            sent[tid] = -1;
        }
    }
    bias[tid]       = b1[e * D_H + tid];
    bias[tid + 256] = b1[e * D_H + tid + 256];
    __syncthreads();

    const char* Xh = (const char*)g_xh;
    const char* Xl = (const char*)g_xl;
    const char* Wh = (const char*)g_w1h + (size_t)e * D_H * D_IN * 2;
    const char* Wl = (const char*)g_w1l + (size_t)e * D_H * D_IN * 2;

    int row  = tid >> 1, half = tid & 1;
    int xrow = srow[row];

    // chunk issue: A = f(kc) 128x32, B = f(nc,kc) 128x32, hi+lo planes
#define G1_ISSUE(ITER, BUF)                                                        \
    do {                                                                           \
        int nc_ = (ITER) >> 3, kc_ = (ITER) & 7;                                   \
        uint32_t d = smb + (BUF) * STAGE + row * RSTRIDE + half * 32;              \
        size_t sa = ((size_t)xrow * D_IN + kc_ * 32 + half * 16) * 2;              \
        size_t sb = ((size_t)(nc_ * 128 + row) * D_IN + kc_ * 32 + half * 16) * 2; \
        cpa16(d,                  Xh + sa);                                        \
        cpa16(d + 16,             Xh + sa + 16);                                   \
        cpa16(d + PLANE,          Xl + sa);                                        \
        cpa16(d + PLANE + 16,     Xl + sa + 16);                                   \
        cpa16(d + 2 * PLANE,      Wh + sb);                                        \
        cpa16(d + 2 * PLANE + 16, Wh + sb + 16);                                   \
        cpa16(d + 3 * PLANE,      Wl + sb);                                        \
        cpa16(d + 3 * PLANE + 16, Wl + sb + 16);                                   \
        CP_COMMIT();                                                               \
    } while (0)

    G1_ISSUE(0, 0);

    uint32_t aoff = (uint32_t)(warpM * 64 + (lane & 15)) * RSTRIDE + ((lane >> 4) << 4);
    uint32_t boff = (uint32_t)(warpN * 32 + (lane & 7) + (((lane >> 4) & 1) << 3)) * RSTRIDE
                  + (((lane >> 3) & 1) << 4);

    float c[4][4][4];

    for (int it = 0; it < 32; it++) {
        int nc = it >> 3, kc = it & 7, buf = it & 1;
        CP_WAIT0();
        __syncthreads();
        if (it + 1 < 32) G1_ISSUE(it + 1, buf ^ 1);
        if (kc == 0) {
#pragma unroll
            for (int mi = 0; mi < 4; mi++)
#pragma unroll
                for (int ni = 0; ni < 4; ni++)
#pragma unroll
                    for (int q = 0; q < 4; q++) c[mi][ni][q] = 0.f;
        }
        uint32_t base   = smb + buf * STAGE;
        uint32_t aBaseH = base + aoff;
        uint32_t aBaseL = aBaseH + PLANE;
        uint32_t bBaseH = base + 2 * PLANE + boff;
        uint32_t bBaseL = bBaseH + PLANE;
#pragma unroll
        for (int k16 = 0; k16 < 2; k16++) {
            uint32_t ah[4][4], al[4][4], bh[4][2], bl[4][2];
#pragma unroll
            for (int mi = 0; mi < 4; mi++) {
                ldsm_x4(ah[mi], aBaseH + mi * (16 * RSTRIDE) + k16 * 32);
                ldsm_x4(al[mi], aBaseL + mi * (16 * RSTRIDE) + k16 * 32);
            }
#pragma unroll
            for (int p = 0; p < 2; p++) {
                uint32_t r4[4];
                ldsm_x4(r4, bBaseH + p * (16 * RSTRIDE) + k16 * 32);
                bh[2 * p][0] = r4[0]; bh[2 * p][1] = r4[1];
                bh[2 * p + 1][0] = r4[2]; bh[2 * p + 1][1] = r4[3];
                ldsm_x4(r4, bBaseL + p * (16 * RSTRIDE) + k16 * 32);
                bl[2 * p][0] = r4[0]; bl[2 * p][1] = r4[1];
                bl[2 * p + 1][0] = r4[2]; bl[2 * p + 1][1] = r4[3];
            }
#pragma unroll
            for (int mi = 0; mi < 4; mi++)
#pragma unroll
                for (int ni = 0; ni < 4; ni++) mma_bf16(c[mi][ni], ah[mi], bh[ni]);
#pragma unroll
            for (int mi = 0; mi < 4; mi++)
#pragma unroll
                for (int ni = 0; ni < 4; ni++) mma_bf16(c[mi][ni], al[mi], bh[ni]);
#pragma unroll
            for (int mi = 0; mi < 4; mi++)
#pragma unroll
                for (int ni = 0; ni < 4; ni++) mma_bf16(c[mi][ni], ah[mi], bl[ni]);
        }
        if (kc == 7) {
#pragma unroll
            for (int mi = 0; mi < 4; mi++) {
                int r0 = warpM * 64 + mi * 16 + lr;
#pragma unroll
                for (int ni = 0; ni < 4; ni++) {
                    int n = nc * 128 + warpN * 32 + ni * 8 + lc2;
                    float b0 = bias[n], b1v = bias[n + 1];
#pragma unroll
                    for (int hh = 0; hh < 2; hh++) {
                        int rr = r0 + hh * 8;
                        if (sent[rr] >= 0) {
                            float v0 = c[mi][ni][hh * 2 + 0] + b0;
                            float v1 = c[mi][ni][hh * 2 + 1] + b1v;
                            v0 = v0 > 0.f ? v0 : 0.f;
                            v1 = v1 > 0.f ? v1 : 0.f;
                            u16 h0, l0, h1, l1;
                            split2(v0, h0, l0);
                            split2(v1, h1, l1);
                            size_t o = (size_t)(beg + m0 + rr) * D_H + n;
                            *(uint32_t*)&g_hh[o] = (uint32_t)h0 | ((uint32_t)h1 << 16);
                            *(uint32_t*)&g_hl[o] = (uint32_t)l0 | ((uint32_t)l1 << 16);
                        }
                    }
                }
            }
        }
    }
#undef G1_ISSUE
}

// ---------------- GEMM2: y = w * (H @ W2 + b2), occ-2 streaming -------------
#define G2_BIAS (2 * STAGE)          // 81920: 256 floats
#define G2_SENT (G2_BIAS + 1024)     // 82944
#define G2_SW   (G2_SENT + 512)      // 83456
#define G2_SIZE (G2_SW + 512)        // 83968

__global__ void __launch_bounds__(256, 2)
gemm2_kernel(const float* __restrict__ b2) {
    int e = blockIdx.y, tile = blockIdx.x;
    int beg = g_offsets[e];
    int cnt = g_offsets[e + 1] - beg;
    int m0  = tile * TM;
    if (m0 >= cnt) return;

    extern __shared__ char sm[];
    uint32_t smb = smem_u32(sm);
    int tid  = threadIdx.x;
    int wid  = tid >> 5, lane = tid & 31;
    int warpM = wid >> 2, warpN = wid & 3;
    int lr = lane >> 2, lc2 = (lane & 3) * 2;

    int*   sent = (int*)(sm + G2_SENT);
    float* swv  = (float*)(sm + G2_SW);
    float* bias = (float*)(sm + G2_BIAS);

    if (tid < TM) {
        int g = beg + m0 + tid;
        if (m0 + tid < cnt) {
            int entry = g_perm[g];
            sent[tid] = entry;
            swv[tid]  = g_topk_w[entry];
        } else {
            sent[tid] = -1;
            swv[tid]  = 0.f;
        }
    }
    if (tid < 256) bias[tid] = b2[e * D_OUT + tid];
    __syncthreads();

    const char* Hh  = (const char*)g_hh;
    const char* Hl  = (const char*)g_hl;
    const char* W2h = (const char*)g_w2h + (size_t)e * D_OUT * D_H * 2;
    const char* W2l = (const char*)g_w2l + (size_t)e * D_OUT * D_H * 2;

    int row  = tid >> 1, half = tid & 1;
    int arow = (m0 + row < cnt) ? (beg + m0 + row) : beg;

#define G2_ISSUE(ITER, BUF)                                                        \
    do {                                                                           \
        int nc_ = (ITER) >> 4, kc_ = (ITER) & 15;                                  \
        uint32_t d = smb + (BUF) * STAGE + row * RSTRIDE + half * 32;              \
        size_t sa = ((size_t)arow * D_H + kc_ * 32 + half * 16) * 2;               \
        size_t sb = ((size_t)(nc_ * 128 + row) * D_H + kc_ * 32 + half * 16) * 2;  \
        cpa16(d,                  Hh + sa);                                        \
        cpa16(d + 16,             Hh + sa + 16);                                   \
        cpa16(d + PLANE,          Hl + sa);                                        \
        cpa16(d + PLANE + 16,     Hl + sa + 16);                                   \
        cpa16(d + 2 * PLANE,      W2h + sb);                                       \
        cpa16(d + 2 * PLANE + 16, W2h + sb + 16);                                  \
        cpa16(d + 3 * PLANE,      W2l + sb);                                       \
        cpa16(d + 3 * PLANE + 16, W2l + sb + 16);                                  \
        CP_COMMIT();                                                               \
    } while (0)

    G2_ISSUE(0, 0);

    uint32_t aoff = (uint32_t)(warpM * 64 + (lane & 15)) * RSTRIDE + ((lane >> 4) << 4);
    uint32_t boff = (uint32_t)(warpN * 32 + (lane & 7) + (((lane >> 4) & 1) << 3)) * RSTRIDE
                  + (((lane >> 3) & 1) << 4);

    float c[4][4][4];

    for (int it = 0; it < 32; it++) {
        int nc = it >> 4, kc = it & 15, buf = it & 1;
        CP_WAIT0();
        __syncthreads();
        if (it + 1 < 32) G2_ISSUE(it + 1, buf ^ 1);
        if (kc == 0) {
#pragma unroll
            for (int mi = 0; mi < 4; mi++)
#pragma unroll
                for (int ni = 0; ni < 4; ni++)
#pragma unroll
                    for (int q = 0; q < 4; q++) c[mi][ni][q] = 0.f;
        }
        uint32_t base   = smb + buf * STAGE;
        uint32_t aBaseH = base + aoff;
        uint32_t aBaseL = aBaseH + PLANE;
        uint32_t bBaseH = base + 2 * PLANE + boff;
        uint32_t bBaseL = bBaseH + PLANE;
#pragma unroll
        for (int k16 = 0; k16 < 2; k16++) {
            uint32_t ah[4][4], al[4][4], bh[4][2], bl[4][2];
#pragma unroll
            for (int mi = 0; mi < 4; mi++) {
                ldsm_x4(ah[mi], aBaseH + mi * (16 * RSTRIDE) + k16 * 32);
                ldsm_x4(al[mi], aBaseL + mi * (16 * RSTRIDE) + k16 * 32);
            }
#pragma unroll
            for (int p = 0; p < 2; p++) {
                uint32_t r4[4];
                ldsm_x4(r4, bBaseH + p * (16 * RSTRIDE) + k16 * 32);
                bh[2 * p][0] = r4[0]; bh[2 * p][1] = r4[1];
                bh[2 * p + 1][0] = r4[2]; bh[2 * p + 1][1] = r4[3];
                ldsm_x4(r4, bBaseL + p * (16 * RSTRIDE) + k16 * 32);
                bl[2 * p][0] = r4[0]; bl[2 * p][1] = r4[1];
                bl[2 * p + 1][0] = r4[2]; bl[2 * p + 1][1] = r4[3];
            }
#pragma unroll
            for (int mi = 0; mi < 4; mi++)
#pragma unroll
                for (int ni = 0; ni < 4; ni++) mma_bf16(c[mi][ni], ah[mi], bh[ni]);
#pragma unroll
            for (int mi = 0; mi < 4; mi++)
#pragma unroll
                for (int ni = 0; ni < 4; ni++) mma_bf16(c[mi][ni], al[mi], bh[ni]);
#pragma unroll
            for (int mi = 0; mi < 4; mi++)
#pragma unroll
                for (int ni = 0; ni < 4; ni++) mma_bf16(c[mi][ni], ah[mi], bl[ni]);
        }
        if (kc == 15) {
#pragma unroll
            for (int mi = 0; mi < 4; mi++) {
                int r0 = warpM * 64 + mi * 16 + lr;
#pragma unroll
                for (int ni = 0; ni < 4; ni++) {
                    int n = nc * 128 + warpN * 32 + ni * 8 + lc2;
                    float b0 = bias[n], b1v = bias[n + 1];
#pragma unroll
                    for (int hh = 0; hh < 2; hh++) {
                        int rr = r0 + hh * 8;
                        int entry = sent[rr];
                        if (entry >= 0) {
                            float w = swv[rr];
                            float2 o;
                            o.x = w * (c[mi][ni][hh * 2 + 0] + b0);
                            o.y = w * (c[mi][ni][hh * 2 + 1] + b1v);
                            *(float2*)&g_y[(size_t)entry * D_OUT + n] = o;
                        }
                    }
                }
            }
        }
    }
#undef G2_ISSUE
}

// ---------------- combine ---------------------------------------------------
__global__ void combine_kernel(float* __restrict__ out) {
    int i = blockIdx.x * blockDim.x + threadIdx.x;
    int b = i >> 6, q = i & 63;
    const float4* y4 = (const float4*)g_y;
    float4 u = y4[(size_t)(b * 2 + 0) * (D_OUT / 4) + q];
    float4 v = y4[(size_t)(b * 2 + 1) * (D_OUT / 4) + q];
    float4 o;
    o.x = u.x + v.x; o.y = u.y + v.y; o.z = u.z + v.z; o.w = u.w + v.w;
    ((float4*)out)[i] = o;
}

// ---------------- launch -----------------------------------------------------
extern "C" void kernel_launch(void* const* d_in, const int* in_sizes, int n_in,
                              void* d_out, int out_size) {
    const float* x  = (const float*)d_in[0];
    const float* Wg = (const float*)d_in[1];
    const float* bg = (const float*)d_in[2];
    const float* W1 = (const float*)d_in[3];
    const float* b1 = (const float*)d_in[4];
    const float* W2 = (const float*)d_in[5];
    const float* b2 = (const float*)d_in[6];
    float* out = (float*)d_out;

    cudaFuncSetAttribute(gemm1_kernel, cudaFuncAttributeMaxDynamicSharedMemorySize, G1_SIZE);
    cudaFuncSetAttribute(gemm2_kernel, cudaFuncAttributeMaxDynamicSharedMemorySize, G2_SIZE);

    reset_kernel<<<1, 32>>>();
    gating_kernel<<<BATCH / 8, 256>>>(x, Wg, bg);
    scan_kernel<<<1, 32>>>();
    scatter_kernel<<<NSLOT / 256, 256>>>();
    pack_x_kernel<<<(BATCH * D_IN / 4) / 256, 256>>>(x);
    pack_transpose_kernel<<<dim3(D_IN / 32, D_H / 32, E_EXP), dim3(32, 8)>>>(W1, 0, D_IN, D_H);
    pack_transpose_kernel<<<dim3(D_H / 32, D_OUT / 32, E_EXP), dim3(32, 8)>>>(W2, 1, D_H, D_OUT);
    gemm1_kernel<<<dim3(NSLOT / TM, E_EXP), 256, G1_SIZE>>>(b1);
    gemm2_kernel<<<dim3(NSLOT / TM, E_EXP), 256, G2_SIZE>>>(b2);
    combine_kernel<<<(BATCH * (D_OUT / 4)) / 256, 256>>>(out);
}

// round 7
// speedup vs baseline: 2.9036x; 1.1548x over previous
#include <cuda_runtime.h>
#include <cuda_bf16.h>
#include <cuda_fp16.h>
#include <math.h>
#include <stdint.h>

typedef unsigned short u16;

#define E_EXP   16
#define TOPK    2
#define D_IN    256
#define D_H     512
#define D_OUT   256
#define BATCH   32768
#define NSLOT   (BATCH * TOPK)
#define TM      128

#define RSTRIDE 80               // padded smem row stride (bytes), 32 fp16 per row
#define PLANE   (128 * RSTRIDE)  // 10240 B
#define STAGE3  (3 * PLANE)      // Ah|Al|Bh = 30720 B per stage

// ---------------- scratch (__device__ globals) ------------------------------
__device__ int   g_counts[E_EXP];
__device__ int   g_offsets[E_EXP + 1];
__device__ int   g_cursor[E_EXP];
__device__ int   g_topk_e[NSLOT];
__device__ float g_topk_w[NSLOT];
__device__ int   g_perm[NSLOT];
__device__ u16   g_xh [(size_t)BATCH * D_IN];        // x hi-fp16 plane
__device__ u16   g_xl [(size_t)BATCH * D_IN];        // x lo-fp16 plane
__device__ u16   g_w1h[(size_t)E_EXP * D_H * D_IN];  // W1^T [e][n][k] fp16
__device__ u16   g_w2h[(size_t)E_EXP * D_OUT * D_H]; // W2^T [e][o][h] fp16
__device__ u16   g_hh [(size_t)NSLOT * D_H];         // H hi-fp16
__device__ u16   g_hl [(size_t)NSLOT * D_H];         // H lo-fp16
__device__ float g_y  [(size_t)NSLOT * D_OUT];

// ---------------- helpers ---------------------------------------------------
__device__ __forceinline__ uint32_t smem_u32(const void* p) {
    uint32_t a;
    asm("{ .reg .u64 t; cvta.to.shared.u64 t, %1; cvt.u32.u64 %0, t; }" : "=r"(a) : "l"(p));
    return a;
}
__device__ __forceinline__ void cpa16(uint32_t dst, const void* src) {
    asm volatile("cp.async.cg.shared.global [%0], [%1], 16;" :: "r"(dst), "l"(src));
}
#define CP_COMMIT() asm volatile("cp.async.commit_group;" ::: "memory")
#define CP_WAIT1()  asm volatile("cp.async.wait_group 1;" ::: "memory")

__device__ __forceinline__ void mma_f16(float c[4], const uint32_t a[4], const uint32_t b[2]) {
    asm volatile(
        "mma.sync.aligned.m16n8k16.row.col.f32.f16.f16.f32 "
        "{%0,%1,%2,%3}, {%4,%5,%6,%7}, {%8,%9}, {%0,%1,%2,%3};"
        : "+f"(c[0]), "+f"(c[1]), "+f"(c[2]), "+f"(c[3])
        : "r"(a[0]), "r"(a[1]), "r"(a[2]), "r"(a[3]), "r"(b[0]), "r"(b[1]));
}
__device__ __forceinline__ void ldsm_x4(uint32_t r[4], uint32_t addr) {
    asm volatile("ldmatrix.sync.aligned.m8n8.x4.shared.b16 {%0,%1,%2,%3}, [%4];"
        : "=r"(r[0]), "=r"(r[1]), "=r"(r[2]), "=r"(r[3]) : "r"(addr));
}
__device__ __forceinline__ void split2h(float v, u16& h, u16& l) {
    __half hb = __float2half(v);
    float r = v - __half2float(hb);
    __half lb = __float2half(r);
    h = __half_as_ushort(hb);
    l = __half_as_ushort(lb);
}
__device__ __forceinline__ u16 to_h(float v) {
    return __half_as_ushort(__float2half(v));
}

// ---------------- reset / gating / scan / scatter ---------------------------
__global__ void reset_kernel() {
    int i = threadIdx.x;
    if (i < E_EXP) g_counts[i] = 0;
}

__global__ void gating_kernel(const float* __restrict__ x,
                              const float* __restrict__ Wg,
                              const float* __restrict__ bg) {
    int warp = (blockIdx.x * blockDim.x + threadIdx.x) >> 5;
    int lane = threadIdx.x & 31;
    if (warp >= BATCH) return;
    const float* xr = x + (size_t)warp * D_IN;

    float acc[E_EXP];
#pragma unroll
    for (int e = 0; e < E_EXP; e++) acc[e] = 0.f;
#pragma unroll
    for (int i = 0; i < D_IN / 32; i++) {
        float xv = xr[i * 32 + lane];
        const float* wr = Wg + (size_t)(i * 32 + lane) * E_EXP;
#pragma unroll
        for (int e = 0; e < E_EXP; e++) acc[e] = fmaf(xv, wr[e], acc[e]);
    }
#pragma unroll
    for (int e = 0; e < E_EXP; e++) {
        float v = acc[e];
        v += __shfl_xor_sync(0xffffffffu, v, 16);
        v += __shfl_xor_sync(0xffffffffu, v, 8);
        v += __shfl_xor_sync(0xffffffffu, v, 4);
        v += __shfl_xor_sync(0xffffffffu, v, 2);
        v += __shfl_xor_sync(0xffffffffu, v, 1);
        acc[e] = v + bg[e];
    }
    if (lane == 0) {
        int i0 = 0; float v0 = acc[0];
#pragma unroll
        for (int e = 1; e < E_EXP; e++)
            if (acc[e] > v0) { v0 = acc[e]; i0 = e; }
        int i1 = -1; float v1 = -3.4e38f;
#pragma unroll
        for (int e = 0; e < E_EXP; e++)
            if (e != i0 && acc[e] > v1) { v1 = acc[e]; i1 = e; }
        float w0 = 1.f / (1.f + expf(v1 - v0));
        g_topk_e[warp * 2 + 0] = i0;
        g_topk_e[warp * 2 + 1] = i1;
        g_topk_w[warp * 2 + 0] = w0;
        g_topk_w[warp * 2 + 1] = 1.f - w0;
        atomicAdd(&g_counts[i0], 1);
        atomicAdd(&g_counts[i1], 1);
    }
}

__global__ void scan_kernel() {
    if (threadIdx.x == 0) {
        int s = 0;
        for (int e = 0; e < E_EXP; e++) {
            g_offsets[e] = s;
            g_cursor[e]  = s;
            s += g_counts[e];
        }
        g_offsets[E_EXP] = s;
    }
}

__global__ void scatter_kernel() {
    __shared__ int hist[E_EXP];
    __shared__ int base[E_EXP];
    int tid = threadIdx.x;
    if (tid < E_EXP) hist[tid] = 0;
    __syncthreads();
    int i = blockIdx.x * 256 + tid;
    int e = g_topk_e[i];
    int rank = atomicAdd(&hist[e], 1);
    __syncthreads();
    if (tid < E_EXP) base[tid] = atomicAdd(&g_cursor[tid], hist[tid]);
    __syncthreads();
    g_perm[base[e] + rank] = i;
}

// ---------------- prep: split planes ----------------------------------------
__global__ void pack_x_kernel(const float* __restrict__ x) {
    size_t i = (size_t)blockIdx.x * blockDim.x + threadIdx.x;
    float4 v = ((const float4*)x)[i];
    u16 h0, h1, h2, h3, l0, l1, l2, l3;
    split2h(v.x, h0, l0); split2h(v.y, h1, l1);
    split2h(v.z, h2, l2); split2h(v.w, h3, l3);
    ((uint2*)g_xh)[i] = make_uint2((uint32_t)h0 | ((uint32_t)h1 << 16),
                                   (uint32_t)h2 | ((uint32_t)h3 << 16));
    ((uint2*)g_xl)[i] = make_uint2((uint32_t)l0 | ((uint32_t)l1 << 16),
                                   (uint32_t)l2 | ((uint32_t)l3 << 16));
}

// in: [e][Kd][Nd] fp32  ->  hi fp16 plane: [e][Nd][Kd]
__global__ void pack_transpose_kernel(const float* __restrict__ in,
                                      int which, int Kd, int Nd) {
    u16* oh = which ? g_w2h : g_w1h;
    __shared__ float t[32][33];
    int e  = blockIdx.z;
    int k0 = blockIdx.x * 32, n0 = blockIdx.y * 32;
    const float* ine = in + (size_t)e * Kd * Nd;
    u16* ohe = oh + (size_t)e * Kd * Nd;
    int tx = threadIdx.x, ty = threadIdx.y;
#pragma unroll
    for (int i = 0; i < 4; i++) {
        int k = k0 + ty + i * 8;
        t[ty + i * 8][tx] = ine[(size_t)k * Nd + n0 + tx];
    }
    __syncthreads();
#pragma unroll
    for (int i = 0; i < 4; i++) {
        int n = n0 + ty + i * 8;
        ohe[(size_t)n * Kd + k0 + tx] = to_h(t[tx][ty + i * 8]);
    }
}

// ---------------- GEMM1: H = relu(X @ W1 + b1), fp16 2-term -----------------
// smem: 3 stages x (Ah|Al|Bh), K-chunk 32
#define G1_BIAS (3 * STAGE3)         // 92160: 512 floats
#define G1_SROW (G1_BIAS + 2048)     // 94208
#define G1_SENT (G1_SROW + 512)      // 94720
#define G1_SIZE (G1_SENT + 512)      // 95232

__global__ void __launch_bounds__(256, 2)
gemm1_kernel(const float* __restrict__ b1) {
    int e = blockIdx.y, tile = blockIdx.x;
    int beg = g_offsets[e];
    int cnt = g_offsets[e + 1] - beg;
    int m0  = tile * TM;
    if (m0 >= cnt) return;

    extern __shared__ char sm[];
    uint32_t smb = smem_u32(sm);
    int tid  = threadIdx.x;
    int wid  = tid >> 5, lane = tid & 31;
    int warpM = wid >> 2, warpN = wid & 3;
    int lr = lane >> 2, lc2 = (lane & 3) * 2;

    int*   srow = (int*)(sm + G1_SROW);
    int*   sent = (int*)(sm + G1_SENT);
    float* bias = (float*)(sm + G1_BIAS);

    if (tid < TM) {
        int g = beg + m0 + tid;
        if (m0 + tid < cnt) {
            int entry = g_perm[g];
            srow[tid] = entry >> 1;
            sent[tid] = entry;
        } else {
            srow[tid] = 0;
            sent[tid] = -1;
        }
    }
    bias[tid]       = b1[e * D_H + tid];
    bias[tid + 256] = b1[e * D_H + tid + 256];
    __syncthreads();

    const char* Xh = (const char*)g_xh;
    const char* Xl = (const char*)g_xl;
    const char* Wh = (const char*)g_w1h + (size_t)e * D_H * D_IN * 2;

    int row  = tid >> 1, half = tid & 1;
    int xrow = srow[row];

#define G1_ISSUE(ITER, BUF)                                                        \
    do {                                                                           \
        int nc_ = (ITER) >> 3, kc_ = (ITER) & 7;                                   \
        uint32_t d = smb + (BUF) * STAGE3 + row * RSTRIDE + half * 32;             \
        size_t sa = ((size_t)xrow * D_IN + kc_ * 32 + half * 16) * 2;              \
        size_t sb = ((size_t)(nc_ * 128 + row) * D_IN + kc_ * 32 + half * 16) * 2; \
        cpa16(d,                  Xh + sa);                                        \
        cpa16(d + 16,             Xh + sa + 16);                                   \
        cpa16(d + PLANE,          Xl + sa);                                        \
        cpa16(d + PLANE + 16,     Xl + sa + 16);                                   \
        cpa16(d + 2 * PLANE,      Wh + sb);                                        \
        cpa16(d + 2 * PLANE + 16, Wh + sb + 16);                                   \
        CP_COMMIT();                                                               \
    } while (0)

    G1_ISSUE(0, 0);
    G1_ISSUE(1, 1);

    uint32_t aoff = (uint32_t)(warpM * 64 + (lane & 15)) * RSTRIDE + ((lane >> 4) << 4);
    uint32_t boff = (uint32_t)(warpN * 32 + (lane & 7) + (((lane >> 4) & 1) << 3)) * RSTRIDE
                  + (((lane >> 3) & 1) << 4);

    float c[4][4][4];
    int buf = 0;

    for (int it = 0; it < 32; it++) {
        int nc = it >> 3, kc = it & 7;
        CP_WAIT1();
        __syncthreads();
        if (it + 2 < 32) {
            int nb = buf + 2; if (nb >= 3) nb -= 3;
            G1_ISSUE(it + 2, nb);
        }
        if (kc == 0) {
#pragma unroll
            for (int mi = 0; mi < 4; mi++)
#pragma unroll
                for (int ni = 0; ni < 4; ni++)
#pragma unroll
                    for (int q = 0; q < 4; q++) c[mi][ni][q] = 0.f;
        }
        uint32_t base   = smb + buf * STAGE3;
        uint32_t aBaseH = base + aoff;
        uint32_t aBaseL = aBaseH + PLANE;
        uint32_t bBaseH = base + 2 * PLANE + boff;
#pragma unroll
        for (int k16 = 0; k16 < 2; k16++) {
            uint32_t ah[4][4], al[4][4], bh[4][2];
#pragma unroll
            for (int mi = 0; mi < 4; mi++) {
                ldsm_x4(ah[mi], aBaseH + mi * (16 * RSTRIDE) + k16 * 32);
                ldsm_x4(al[mi], aBaseL + mi * (16 * RSTRIDE) + k16 * 32);
            }
#pragma unroll
            for (int p = 0; p < 2; p++) {
                uint32_t r4[4];
                ldsm_x4(r4, bBaseH + p * (16 * RSTRIDE) + k16 * 32);
                bh[2 * p][0] = r4[0]; bh[2 * p][1] = r4[1];
                bh[2 * p + 1][0] = r4[2]; bh[2 * p + 1][1] = r4[3];
            }
#pragma unroll
            for (int mi = 0; mi < 4; mi++)
#pragma unroll
                for (int ni = 0; ni < 4; ni++) mma_f16(c[mi][ni], ah[mi], bh[ni]);
#pragma unroll
            for (int mi = 0; mi < 4; mi++)
#pragma unroll
                for (int ni = 0; ni < 4; ni++) mma_f16(c[mi][ni], al[mi], bh[ni]);
        }
        if (kc == 7) {
#pragma unroll
            for (int mi = 0; mi < 4; mi++) {
                int r0 = warpM * 64 + mi * 16 + lr;
#pragma unroll
                for (int ni = 0; ni < 4; ni++) {
                    int n = nc * 128 + warpN * 32 + ni * 8 + lc2;
                    float b0 = bias[n], b1v = bias[n + 1];
#pragma unroll
                    for (int hh = 0; hh < 2; hh++) {
                        int rr = r0 + hh * 8;
                        if (sent[rr] >= 0) {
                            float v0 = c[mi][ni][hh * 2 + 0] + b0;
                            float v1 = c[mi][ni][hh * 2 + 1] + b1v;
                            v0 = v0 > 0.f ? v0 : 0.f;
                            v1 = v1 > 0.f ? v1 : 0.f;
                            u16 h0, l0, h1, l1;
                            split2h(v0, h0, l0);
                            split2h(v1, h1, l1);
                            size_t o = (size_t)(beg + m0 + rr) * D_H + n;
                            *(uint32_t*)&g_hh[o] = (uint32_t)h0 | ((uint32_t)h1 << 16);
                            *(uint32_t*)&g_hl[o] = (uint32_t)l0 | ((uint32_t)l1 << 16);
                        }
                    }
                }
            }
        }
        if (++buf == 3) buf = 0;
    }
#undef G1_ISSUE
}

// ---------------- GEMM2: y = w * (H @ W2 + b2), fp16 2-term -----------------
#define G2_BIAS (3 * STAGE3)         // 92160: 256 floats
#define G2_SENT (G2_BIAS + 1024)     // 93184
#define G2_SW   (G2_SENT + 512)      // 93696
#define G2_SIZE (G2_SW + 512)        // 94208

__global__ void __launch_bounds__(256, 2)
gemm2_kernel(const float* __restrict__ b2) {
    int e = blockIdx.y, tile = blockIdx.x;
    int beg = g_offsets[e];
    int cnt = g_offsets[e + 1] - beg;
    int m0  = tile * TM;
    if (m0 >= cnt) return;

    extern __shared__ char sm[];
    uint32_t smb = smem_u32(sm);
    int tid  = threadIdx.x;
    int wid  = tid >> 5, lane = tid & 31;
    int warpM = wid >> 2, warpN = wid & 3;
    int lr = lane >> 2, lc2 = (lane & 3) * 2;

    int*   sent = (int*)(sm + G2_SENT);
    float* swv  = (float*)(sm + G2_SW);
    float* bias = (float*)(sm + G2_BIAS);

    if (tid < TM) {
        int g = beg + m0 + tid;
        if (m0 + tid < cnt) {
            int entry = g_perm[g];
            sent[tid] = entry;
            swv[tid]  = g_topk_w[entry];
        } else {
            sent[tid] = -1;
            swv[tid]  = 0.f;
        }
    }
    if (tid < 256) bias[tid] = b2[e * D_OUT + tid];
    __syncthreads();

    const char* Hh  = (const char*)g_hh;
    const char* Hl  = (const char*)g_hl;
    const char* W2h = (const char*)g_w2h + (size_t)e * D_OUT * D_H * 2;

    int row  = tid >> 1, half = tid & 1;
    int arow = (m0 + row < cnt) ? (beg + m0 + row) : beg;

#define G2_ISSUE(ITER, BUF)                                                        \
    do {                                                                           \
        int nc_ = (ITER) >> 4, kc_ = (ITER) & 15;                                  \
        uint32_t d = smb + (BUF) * STAGE3 + row * RSTRIDE + half * 32;             \
        size_t sa = ((size_t)arow * D_H + kc_ * 32 + half * 16) * 2;               \
        size_t sb = ((size_t)(nc_ * 128 + row) * D_H + kc_ * 32 + half * 16) * 2;  \
        cpa16(d,                  Hh + sa);                                        \
        cpa16(d + 16,             Hh + sa + 16);                                   \
        cpa16(d + PLANE,          Hl + sa);                                        \
        cpa16(d + PLANE + 16,     Hl + sa + 16);                                   \
        cpa16(d + 2 * PLANE,      W2h + sb);                                       \
        cpa16(d + 2 * PLANE + 16, W2h + sb + 16);                                  \
        CP_COMMIT();                                                               \
    } while (0)

    G2_ISSUE(0, 0);
    G2_ISSUE(1, 1);

    uint32_t aoff = (uint32_t)(warpM * 64 + (lane & 15)) * RSTRIDE + ((lane >> 4) << 4);
    uint32_t boff = (uint32_t)(warpN * 32 + (lane & 7) + (((lane >> 4) & 1) << 3)) * RSTRIDE
                  + (((lane >> 3) & 1) << 4);

    float c[4][4][4];
    int buf = 0;

    for (int it = 0; it < 32; it++) {
        int nc = it >> 4, kc = it & 15;
        CP_WAIT1();
        __syncthreads();
        if (it + 2 < 32) {
            int nb = buf + 2; if (nb >= 3) nb -= 3;
            G2_ISSUE(it + 2, nb);
        }
        if (kc == 0) {
#pragma unroll
            for (int mi = 0; mi < 4; mi++)
#pragma unroll
                for (int ni = 0; ni < 4; ni++)
#pragma unroll
                    for (int q = 0; q < 4; q++) c[mi][ni][q] = 0.f;
        }
        uint32_t base   = smb + buf * STAGE3;
        uint32_t aBaseH = base + aoff;
        uint32_t aBaseL = aBaseH + PLANE;
        uint32_t bBaseH = base + 2 * PLANE + boff;
#pragma unroll
        for (int k16 = 0; k16 < 2; k16++) {
            uint32_t ah[4][4], al[4][4], bh[4][2];
#pragma unroll
            for (int mi = 0; mi < 4; mi++) {
                ldsm_x4(ah[mi], aBaseH + mi * (16 * RSTRIDE) + k16 * 32);
                ldsm_x4(al[mi], aBaseL + mi * (16 * RSTRIDE) + k16 * 32);
            }
#pragma unroll
            for (int p = 0; p < 2; p++) {
                uint32_t r4[4];
                ldsm_x4(r4, bBaseH + p * (16 * RSTRIDE) + k16 * 32);
                bh[2 * p][0] = r4[0]; bh[2 * p][1] = r4[1];
                bh[2 * p + 1][0] = r4[2]; bh[2 * p + 1][1] = r4[3];
            }
#pragma unroll
            for (int mi = 0; mi < 4; mi++)
#pragma unroll
                for (int ni = 0; ni < 4; ni++) mma_f16(c[mi][ni], ah[mi], bh[ni]);
#pragma unroll
            for (int mi = 0; mi < 4; mi++)
#pragma unroll
                for (int ni = 0; ni < 4; ni++) mma_f16(c[mi][ni], al[mi], bh[ni]);
        }
        if (kc == 15) {
#pragma unroll
            for (int mi = 0; mi < 4; mi++) {
                int r0 = warpM * 64 + mi * 16 + lr;
#pragma unroll
                for (int ni = 0; ni < 4; ni++) {
                    int n = nc * 128 + warpN * 32 + ni * 8 + lc2;
                    float b0 = bias[n], b1v = bias[n + 1];
#pragma unroll
                    for (int hh = 0; hh < 2; hh++) {
                        int rr = r0 + hh * 8;
                        int entry = sent[rr];
                        if (entry >= 0) {
                            float w = swv[rr];
                            float2 o;
                            o.x = w * (c[mi][ni][hh * 2 + 0] + b0);
                            o.y = w * (c[mi][ni][hh * 2 + 1] + b1v);
                            *(float2*)&g_y[(size_t)entry * D_OUT + n] = o;
                        }
                    }
                }
            }
        }
        if (++buf == 3) buf = 0;
    }
#undef G2_ISSUE
}

// ---------------- combine ---------------------------------------------------
__global__ void combine_kernel(float* __restrict__ out) {
    int i = blockIdx.x * blockDim.x + threadIdx.x;
    int b = i >> 6, q = i & 63;
    const float4* y4 = (const float4*)g_y;
    float4 u = y4[(size_t)(b * 2 + 0) * (D_OUT / 4) + q];
    float4 v = y4[(size_t)(b * 2 + 1) * (D_OUT / 4) + q];
    float4 o;
    o.x = u.x + v.x; o.y = u.y + v.y; o.z = u.z + v.z; o.w = u.w + v.w;
    ((float4*)out)[i] = o;
}

// ---------------- launch -----------------------------------------------------
extern "C" void kernel_launch(void* const* d_in, const int* in_sizes, int n_in,
                              void* d_out, int out_size) {
    const float* x  = (const float*)d_in[0];
    const float* Wg = (const float*)d_in[1];
    const float* bg = (const float*)d_in[2];
    const float* W1 = (const float*)d_in[3];
    const float* b1 = (const float*)d_in[4];
    const float* W2 = (const float*)d_in[5];
    const float* b2 = (const float*)d_in[6];
    float* out = (float*)d_out;

    cudaFuncSetAttribute(gemm1_kernel, cudaFuncAttributeMaxDynamicSharedMemorySize, G1_SIZE);
    cudaFuncSetAttribute(gemm2_kernel, cudaFuncAttributeMaxDynamicSharedMemorySize, G2_SIZE);

    reset_kernel<<<1, 32>>>();
    gating_kernel<<<BATCH / 8, 256>>>(x, Wg, bg);
    scan_kernel<<<1, 32>>>();
    scatter_kernel<<<NSLOT / 256, 256>>>();
    pack_x_kernel<<<(BATCH * D_IN / 4) / 256, 256>>>(x);
    pack_transpose_kernel<<<dim3(D_IN / 32, D_H / 32, E_EXP), dim3(32, 8)>>>(W1, 0, D_IN, D_H);
    pack_transpose_kernel<<<dim3(D_H / 32, D_OUT / 32, E_EXP), dim3(32, 8)>>>(W2, 1, D_H, D_OUT);
    gemm1_kernel<<<dim3(NSLOT / TM, E_EXP), 256, G1_SIZE>>>(b1);
    gemm2_kernel<<<dim3(NSLOT / TM, E_EXP), 256, G2_SIZE>>>(b2);
    combine_kernel<<<(BATCH * (D_OUT / 4)) / 256, 256>>>(out);
}

// round 8
// speedup vs baseline: 3.6050x; 1.2415x over previous
#include <cuda_runtime.h>
#include <cuda_fp16.h>
#include <math.h>
#include <stdint.h>

typedef unsigned short u16;

#define E_EXP   16
#define TOPK    2
#define D_IN    256
#define D_H     512
#define D_OUT   256
#define BATCH   32768
#define NSLOT   (BATCH * TOPK)
#define TM      128

#define RSTRIDE 80               // padded smem row stride (bytes), 32 fp16 per row
#define PLANE   (128 * RSTRIDE)  // 10240 B
#define STAGE2  (2 * PLANE)      // A|B = 20480 B per stage

// ---------------- scratch (__device__ globals) ------------------------------
__device__ int   g_counts[E_EXP];
__device__ int   g_offsets[E_EXP + 1];
__device__ int   g_cursor[E_EXP];
__device__ int   g_topk_e[NSLOT];
__device__ float g_topk_w[NSLOT];
__device__ int   g_perm[NSLOT];
__device__ u16   g_xh [(size_t)BATCH * D_IN];        // x fp16
__device__ u16   g_w1h[(size_t)E_EXP * D_H * D_IN];  // W1^T [e][n][k] fp16
__device__ u16   g_w2h[(size_t)E_EXP * D_OUT * D_H]; // W2^T [e][o][h] fp16
__device__ u16   g_hh [(size_t)NSLOT * D_H];         // H fp16
__device__ float g_y  [(size_t)NSLOT * D_OUT];

// ---------------- helpers ---------------------------------------------------
__device__ __forceinline__ uint32_t smem_u32(const void* p) {
    uint32_t a;
    asm("{ .reg .u64 t; cvta.to.shared.u64 t, %1; cvt.u32.u64 %0, t; }" : "=r"(a) : "l"(p));
    return a;
}
__device__ __forceinline__ void cpa16(uint32_t dst, const void* src) {
    asm volatile("cp.async.cg.shared.global [%0], [%1], 16;" :: "r"(dst), "l"(src));
}
#define CP_COMMIT() asm volatile("cp.async.commit_group;" ::: "memory")
#define CP_WAIT1()  asm volatile("cp.async.wait_group 1;" ::: "memory")

__device__ __forceinline__ void mma_f16(float c[4], const uint32_t a[4], const uint32_t b[2]) {
    asm volatile(
        "mma.sync.aligned.m16n8k16.row.col.f32.f16.f16.f32 "
        "{%0,%1,%2,%3}, {%4,%5,%6,%7}, {%8,%9}, {%0,%1,%2,%3};"
        : "+f"(c[0]), "+f"(c[1]), "+f"(c[2]), "+f"(c[3])
        : "r"(a[0]), "r"(a[1]), "r"(a[2]), "r"(a[3]), "r"(b[0]), "r"(b[1]));
}
__device__ __forceinline__ void ldsm_x4(uint32_t r[4], uint32_t addr) {
    asm volatile("ldmatrix.sync.aligned.m8n8.x4.shared.b16 {%0,%1,%2,%3}, [%4];"
        : "=r"(r[0]), "=r"(r[1]), "=r"(r[2]), "=r"(r[3]) : "r"(addr));
}
__device__ __forceinline__ u16 to_h(float v) {
    return __half_as_ushort(__float2half(v));
}

// ---------------- reset / gating / scan / scatter ---------------------------
__global__ void reset_kernel() {
    int i = threadIdx.x;
    if (i < E_EXP) g_counts[i] = 0;
}

__global__ void gating_kernel(const float* __restrict__ x,
                              const float* __restrict__ Wg,
                              const float* __restrict__ bg) {
    int warp = (blockIdx.x * blockDim.x + threadIdx.x) >> 5;
    int lane = threadIdx.x & 31;
    if (warp >= BATCH) return;
    const float* xr = x + (size_t)warp * D_IN;

    float acc[E_EXP];
#pragma unroll
    for (int e = 0; e < E_EXP; e++) acc[e] = 0.f;
#pragma unroll
    for (int i = 0; i < D_IN / 32; i++) {
        float xv = xr[i * 32 + lane];
        const float* wr = Wg + (size_t)(i * 32 + lane) * E_EXP;
#pragma unroll
        for (int e = 0; e < E_EXP; e++) acc[e] = fmaf(xv, wr[e], acc[e]);
    }
#pragma unroll
    for (int e = 0; e < E_EXP; e++) {
        float v = acc[e];
        v += __shfl_xor_sync(0xffffffffu, v, 16);
        v += __shfl_xor_sync(0xffffffffu, v, 8);
        v += __shfl_xor_sync(0xffffffffu, v, 4);
        v += __shfl_xor_sync(0xffffffffu, v, 2);
        v += __shfl_xor_sync(0xffffffffu, v, 1);
        acc[e] = v + bg[e];
    }
    if (lane == 0) {
        int i0 = 0; float v0 = acc[0];
#pragma unroll
        for (int e = 1; e < E_EXP; e++)
            if (acc[e] > v0) { v0 = acc[e]; i0 = e; }
        int i1 = -1; float v1 = -3.4e38f;
#pragma unroll
        for (int e = 0; e < E_EXP; e++)
            if (e != i0 && acc[e] > v1) { v1 = acc[e]; i1 = e; }
        float w0 = 1.f / (1.f + expf(v1 - v0));
        g_topk_e[warp * 2 + 0] = i0;
        g_topk_e[warp * 2 + 1] = i1;
        g_topk_w[warp * 2 + 0] = w0;
        g_topk_w[warp * 2 + 1] = 1.f - w0;
        atomicAdd(&g_counts[i0], 1);
        atomicAdd(&g_counts[i1], 1);
    }
}

__global__ void scan_kernel() {
    if (threadIdx.x == 0) {
        int s = 0;
        for (int e = 0; e < E_EXP; e++) {
            g_offsets[e] = s;
            g_cursor[e]  = s;
            s += g_counts[e];
        }
        g_offsets[E_EXP] = s;
    }
}

__global__ void scatter_kernel() {
    __shared__ int hist[E_EXP];
    __shared__ int base[E_EXP];
    int tid = threadIdx.x;
    if (tid < E_EXP) hist[tid] = 0;
    __syncthreads();
    int i = blockIdx.x * 256 + tid;
    int e = g_topk_e[i];
    int rank = atomicAdd(&hist[e], 1);
    __syncthreads();
    if (tid < E_EXP) base[tid] = atomicAdd(&g_cursor[tid], hist[tid]);
    __syncthreads();
    g_perm[base[e] + rank] = i;
}

// ---------------- prep: fp16 quantize ---------------------------------------
__global__ void pack_x_kernel(const float* __restrict__ x) {
    size_t i = (size_t)blockIdx.x * blockDim.x + threadIdx.x;
    float4 v = ((const float4*)x)[i];
    uint2 o;
    o.x = (uint32_t)to_h(v.x) | ((uint32_t)to_h(v.y) << 16);
    o.y = (uint32_t)to_h(v.z) | ((uint32_t)to_h(v.w) << 16);
    ((uint2*)g_xh)[i] = o;
}

// in: [e][Kd][Nd] fp32  ->  fp16 plane: [e][Nd][Kd]
__global__ void pack_transpose_kernel(const float* __restrict__ in,
                                      int which, int Kd, int Nd) {
    u16* oh = which ? g_w2h : g_w1h;
    __shared__ float t[32][33];
    int e  = blockIdx.z;
    int k0 = blockIdx.x * 32, n0 = blockIdx.y * 32;
    const float* ine = in + (size_t)e * Kd * Nd;
    u16* ohe = oh + (size_t)e * Kd * Nd;
    int tx = threadIdx.x, ty = threadIdx.y;
#pragma unroll
    for (int i = 0; i < 4; i++) {
        int k = k0 + ty + i * 8;
        t[ty + i * 8][tx] = ine[(size_t)k * Nd + n0 + tx];
    }
    __syncthreads();
#pragma unroll
    for (int i = 0; i < 4; i++) {
        int n = n0 + ty + i * 8;
        ohe[(size_t)n * Kd + k0 + tx] = to_h(t[tx][ty + i * 8]);
    }
}

// ---------------- GEMM1: H = relu(X @ W1 + b1), fp16 1-term -----------------
// smem: 3 stages x (A|B), K-chunk 32
#define G1_BIAS (3 * STAGE2)         // 61440: 512 floats
#define G1_SROW (G1_BIAS + 2048)     // 63488
#define G1_SENT (G1_SROW + 512)      // 64000
#define G1_SIZE (G1_SENT + 512)      // 64512

__global__ void __launch_bounds__(256, 2)
gemm1_kernel(const float* __restrict__ b1) {
    int e = blockIdx.y, tile = blockIdx.x;
    int beg = g_offsets[e];
    int cnt = g_offsets[e + 1] - beg;
    int m0  = tile * TM;
    if (m0 >= cnt) return;

    extern __shared__ char sm[];
    uint32_t smb = smem_u32(sm);
    int tid  = threadIdx.x;
    int wid  = tid >> 5, lane = tid & 31;
    int warpM = wid >> 2, warpN = wid & 3;
    int lr = lane >> 2, lc2 = (lane & 3) * 2;

    int*   srow = (int*)(sm + G1_SROW);
    int*   sent = (int*)(sm + G1_SENT);
    float* bias = (float*)(sm + G1_BIAS);

    if (tid < TM) {
        int g = beg + m0 + tid;
        if (m0 + tid < cnt) {
            int entry = g_perm[g];
            srow[tid] = entry >> 1;
            sent[tid] = entry;
        } else {
            srow[tid] = 0;
            sent[tid] = -1;
        }
    }
    bias[tid]       = b1[e * D_H + tid];
    bias[tid + 256] = b1[e * D_H + tid + 256];
    __syncthreads();

    const char* Xh = (const char*)g_xh;
    const char* Wh = (const char*)g_w1h + (size_t)e * D_H * D_IN * 2;

    int row  = tid >> 1, half = tid & 1;
    int xrow = srow[row];

#define G1_ISSUE(ITER, BUF)                                                        \
    do {                                                                           \
        int nc_ = (ITER) >> 3, kc_ = (ITER) & 7;                                   \
        uint32_t d = smb + (BUF) * STAGE2 + row * RSTRIDE + half * 32;             \
        size_t sa = ((size_t)xrow * D_IN + kc_ * 32 + half * 16) * 2;              \
        size_t sb = ((size_t)(nc_ * 128 + row) * D_IN + kc_ * 32 + half * 16) * 2; \
        cpa16(d,              Xh + sa);                                            \
        cpa16(d + 16,         Xh + sa + 16);                                       \
        cpa16(d + PLANE,      Wh + sb);                                            \
        cpa16(d + PLANE + 16, Wh + sb + 16);                                       \
        CP_COMMIT();                                                               \
    } while (0)

    G1_ISSUE(0, 0);
    G1_ISSUE(1, 1);

    uint32_t aoff = (uint32_t)(warpM * 64 + (lane & 15)) * RSTRIDE + ((lane >> 4) << 4);
    uint32_t boff = (uint32_t)(warpN * 32 + (lane & 7) + (((lane >> 4) & 1) << 3)) * RSTRIDE
                  + (((lane >> 3) & 1) << 4);

    float c[4][4][4];
    int buf = 0;

    for (int it = 0; it < 32; it++) {
        int nc = it >> 3, kc = it & 7;
        CP_WAIT1();
        __syncthreads();
        if (it + 2 < 32) {
            int nb = buf + 2; if (nb >= 3) nb -= 3;
            G1_ISSUE(it + 2, nb);
        }
        if (kc == 0) {
#pragma unroll
            for (int mi = 0; mi < 4; mi++)
#pragma unroll
                for (int ni = 0; ni < 4; ni++)
#pragma unroll
                    for (int q = 0; q < 4; q++) c[mi][ni][q] = 0.f;
        }
        uint32_t base   = smb + buf * STAGE2;
        uint32_t aBase  = base + aoff;
        uint32_t bBase  = base + PLANE + boff;
#pragma unroll
        for (int k16 = 0; k16 < 2; k16++) {
            uint32_t ah[4][4], bh[4][2];
#pragma unroll
            for (int mi = 0; mi < 4; mi++)
                ldsm_x4(ah[mi], aBase + mi * (16 * RSTRIDE) + k16 * 32);
#pragma unroll
            for (int p = 0; p < 2; p++) {
                uint32_t r4[4];
                ldsm_x4(r4, bBase + p * (16 * RSTRIDE) + k16 * 32);
                bh[2 * p][0] = r4[0]; bh[2 * p][1] = r4[1];
                bh[2 * p + 1][0] = r4[2]; bh[2 * p + 1][1] = r4[3];
            }
#pragma unroll
            for (int mi = 0; mi < 4; mi++)
#pragma unroll
                for (int ni = 0; ni < 4; ni++) mma_f16(c[mi][ni], ah[mi], bh[ni]);
        }
        if (kc == 7) {
#pragma unroll
            for (int mi = 0; mi < 4; mi++) {
                int r0 = warpM * 64 + mi * 16 + lr;
#pragma unroll
                for (int ni = 0; ni < 4; ni++) {
                    int n = nc * 128 + warpN * 32 + ni * 8 + lc2;
                    float b0 = bias[n], b1v = bias[n + 1];
#pragma unroll
                    for (int hh = 0; hh < 2; hh++) {
                        int rr = r0 + hh * 8;
                        if (sent[rr] >= 0) {
                            float v0 = c[mi][ni][hh * 2 + 0] + b0;
                            float v1 = c[mi][ni][hh * 2 + 1] + b1v;
                            v0 = v0 > 0.f ? v0 : 0.f;
                            v1 = v1 > 0.f ? v1 : 0.f;
                            size_t o = (size_t)(beg + m0 + rr) * D_H + n;
                            *(uint32_t*)&g_hh[o] =
                                (uint32_t)to_h(v0) | ((uint32_t)to_h(v1) << 16);
                        }
                    }
                }
            }
        }
        if (++buf == 3) buf = 0;
    }
#undef G1_ISSUE
}

// ---------------- GEMM2: y = w * (H @ W2 + b2), fp16 1-term -----------------
#define G2_BIAS (3 * STAGE2)         // 61440: 256 floats
#define G2_SENT (G2_BIAS + 1024)     // 62464
#define G2_SW   (G2_SENT + 512)      // 62976
#define G2_SIZE (G2_SW + 512)        // 63488

__global__ void __launch_bounds__(256, 2)
gemm2_kernel(const float* __restrict__ b2) {
    int e = blockIdx.y, tile = blockIdx.x;
    int beg = g_offsets[e];
    int cnt = g_offsets[e + 1] - beg;
    int m0  = tile * TM;
    if (m0 >= cnt) return;

    extern __shared__ char sm[];
    uint32_t smb = smem_u32(sm);
    int tid  = threadIdx.x;
    int wid  = tid >> 5, lane = tid & 31;
    int warpM = wid >> 2, warpN = wid & 3;
    int lr = lane >> 2, lc2 = (lane & 3) * 2;

    int*   sent = (int*)(sm + G2_SENT);
    float* swv  = (float*)(sm + G2_SW);
    float* bias = (float*)(sm + G2_BIAS);

    if (tid < TM) {
        int g = beg + m0 + tid;
        if (m0 + tid < cnt) {
            int entry = g_perm[g];
            sent[tid] = entry;
            swv[tid]  = g_topk_w[entry];
        } else {
            sent[tid] = -1;
            swv[tid]  = 0.f;
        }
    }
    if (tid < 256) bias[tid] = b2[e * D_OUT + tid];
    __syncthreads();

    const char* Hh  = (const char*)g_hh;
    const char* W2h = (const char*)g_w2h + (size_t)e * D_OUT * D_H * 2;

    int row  = tid >> 1, half = tid & 1;
    int arow = (m0 + row < cnt) ? (beg + m0 + row) : beg;

#define G2_ISSUE(ITER, BUF)                                                        \
    do {                                                                           \
        int nc_ = (ITER) >> 4, kc_ = (ITER) & 15;                                  \
        uint32_t d = smb + (BUF) * STAGE2 + row * RSTRIDE + half * 32;             \
        size_t sa = ((size_t)arow * D_H + kc_ * 32 + half * 16) * 2;               \
        size_t sb = ((size_t)(nc_ * 128 + row) * D_H + kc_ * 32 + half * 16) * 2;  \
        cpa16(d,              Hh + sa);                                            \
        cpa16(d + 16,         Hh + sa + 16);                                       \
        cpa16(d + PLANE,      W2h + sb);                                           \
        cpa16(d + PLANE + 16, W2h + sb + 16);                                      \
        CP_COMMIT();                                                               \
    } while (0)

    G2_ISSUE(0, 0);
    G2_ISSUE(1, 1);

    uint32_t aoff = (uint32_t)(warpM * 64 + (lane & 15)) * RSTRIDE + ((lane >> 4) << 4);
    uint32_t boff = (uint32_t)(warpN * 32 + (lane & 7) + (((lane >> 4) & 1) << 3)) * RSTRIDE
                  + (((lane >> 3) & 1) << 4);

    float c[4][4][4];
    int buf = 0;

    for (int it = 0; it < 32; it++) {
        int nc = it >> 4, kc = it & 15;
        CP_WAIT1();
        __syncthreads();
        if (it + 2 < 32) {
            int nb = buf + 2; if (nb >= 3) nb -= 3;
            G2_ISSUE(it + 2, nb);
        }
        if (kc == 0) {
#pragma unroll
            for (int mi = 0; mi < 4; mi++)
#pragma unroll
                for (int ni = 0; ni < 4; ni++)
#pragma unroll
                    for (int q = 0; q < 4; q++) c[mi][ni][q] = 0.f;
        }
        uint32_t base  = smb + buf * STAGE2;
        uint32_t aBase = base + aoff;
        uint32_t bBase = base + PLANE + boff;
#pragma unroll
        for (int k16 = 0; k16 < 2; k16++) {
            uint32_t ah[4][4], bh[4][2];
#pragma unroll
            for (int mi = 0; mi < 4; mi++)
                ldsm_x4(ah[mi], aBase + mi * (16 * RSTRIDE) + k16 * 32);
#pragma unroll
            for (int p = 0; p < 2; p++) {
                uint32_t r4[4];
                ldsm_x4(r4, bBase + p * (16 * RSTRIDE) + k16 * 32);
                bh[2 * p][0] = r4[0]; bh[2 * p][1] = r4[1];
                bh[2 * p + 1][0] = r4[2]; bh[2 * p + 1][1] = r4[3];
            }
#pragma unroll
            for (int mi = 0; mi < 4; mi++)
#pragma unroll
                for (int ni = 0; ni < 4; ni++) mma_f16(c[mi][ni], ah[mi], bh[ni]);
        }
        if (kc == 15) {
#pragma unroll
            for (int mi = 0; mi < 4; mi++) {
                int r0 = warpM * 64 + mi * 16 + lr;
#pragma unroll
                for (int ni = 0; ni < 4; ni++) {
                    int n = nc * 128 + warpN * 32 + ni * 8 + lc2;
                    float b0 = bias[n], b1v = bias[n + 1];
#pragma unroll
                    for (int hh = 0; hh < 2; hh++) {
                        int rr = r0 + hh * 8;
                        int entry = sent[rr];
                        if (entry >= 0) {
                            float w = swv[rr];
                            float2 o;
                            o.x = w * (c[mi][ni][hh * 2 + 0] + b0);
                            o.y = w * (c[mi][ni][hh * 2 + 1] + b1v);
                            *(float2*)&g_y[(size_t)entry * D_OUT + n] = o;
                        }
                    }
                }
            }
        }
        if (++buf == 3) buf = 0;
    }
#undef G2_ISSUE
}

// ---------------- combine ---------------------------------------------------
__global__ void combine_kernel(float* __restrict__ out) {
    int i = blockIdx.x * blockDim.x + threadIdx.x;
    int b = i >> 6, q = i & 63;
    const float4* y4 = (const float4*)g_y;
    float4 u = y4[(size_t)(b * 2 + 0) * (D_OUT / 4) + q];
    float4 v = y4[(size_t)(b * 2 + 1) * (D_OUT / 4) + q];
    float4 o;
    o.x = u.x + v.x; o.y = u.y + v.y; o.z = u.z + v.z; o.w = u.w + v.w;
    ((float4*)out)[i] = o;
}

// ---------------- launch -----------------------------------------------------
extern "C" void kernel_launch(void* const* d_in, const int* in_sizes, int n_in,
                              void* d_out, int out_size) {
    const float* x  = (const float*)d_in[0];
    const float* Wg = (const float*)d_in[1];
    const float* bg = (const float*)d_in[2];
    const float* W1 = (const float*)d_in[3];
    const float* b1 = (const float*)d_in[4];
    const float* W2 = (const float*)d_in[5];
    const float* b2 = (const float*)d_in[6];
    float* out = (float*)d_out;

    cudaFuncSetAttribute(gemm1_kernel, cudaFuncAttributeMaxDynamicSharedMemorySize, G1_SIZE);
    cudaFuncSetAttribute(gemm2_kernel, cudaFuncAttributeMaxDynamicSharedMemorySize, G2_SIZE);

    reset_kernel<<<1, 32>>>();
    gating_kernel<<<BATCH / 8, 256>>>(x, Wg, bg);
    scan_kernel<<<1, 32>>>();
    scatter_kernel<<<NSLOT / 256, 256>>>();
    pack_x_kernel<<<(BATCH * D_IN / 4) / 256, 256>>>(x);
    pack_transpose_kernel<<<dim3(D_IN / 32, D_H / 32, E_EXP), dim3(32, 8)>>>(W1, 0, D_IN, D_H);
    pack_transpose_kernel<<<dim3(D_H / 32, D_OUT / 32, E_EXP), dim3(32, 8)>>>(W2, 1, D_H, D_OUT);
    gemm1_kernel<<<dim3(NSLOT / TM, E_EXP), 256, G1_SIZE>>>(b1);
    gemm2_kernel<<<dim3(NSLOT / TM, E_EXP), 256, G2_SIZE>>>(b2);
    combine_kernel<<<(BATCH * (D_OUT / 4)) / 256, 256>>>(out);
}